// round 10
// baseline (speedup 1.0000x reference)
#include <cuda_runtime.h>
#include <math.h>
#include <stdint.h>

#define BB     8
#define RDIM   64
#define CDIM   16
#define DDIM   128
#define NPAIR  2016
#define PPB    8
#define NGRP   (NPAIR / PPB)   // 252
#define NT     512
#define AP     132             // padded pitch (floats)
#define KP3    264             // P3 staging pitch (mod 32 == 8)
#define KP5    2056            // P5 staging pitch (mod 32 == 8)

// scale = 1/sqrt(D*C) = 1/sqrt(2048)
#define SCALE  0.022097086912079608f

__device__ float g_k [BB * RDIM * CDIM * DDIM];   // K projection, tf32-rounded (4MB)
__device__ float g_bi[BB * RDIM * CDIM * DDIM];   // batch_input, tf32-rounded (4MB)
__device__ float g_wt[4 * DDIM * DDIM];           // W^T tf32-rounded: hW,qW,gW,s1W

// ---------------------------------------------------------------------------
static __device__ __forceinline__ uint32_t rna_tf32(float v) {
    uint32_t r;
    asm("cvt.rna.tf32.f32 %0, %1;" : "=r"(r) : "f"(v));
    return r;
}

static __device__ __forceinline__ void mma8(float c[4], const uint32_t a[4],
                                            const uint32_t b[2]) {
    asm volatile(
        "mma.sync.aligned.m16n8k8.row.col.f32.tf32.tf32.f32 "
        "{%0,%1,%2,%3}, {%4,%5,%6,%7}, {%8,%9}, {%0,%1,%2,%3};"
        : "+f"(c[0]), "+f"(c[1]), "+f"(c[2]), "+f"(c[3])
        : "r"(a[0]), "r"(a[1]), "r"(a[2]), "r"(a[3]), "r"(b[0]), "r"(b[1]));
}

__device__ __forceinline__ float warp_sum(float v) {
    v += __shfl_xor_sync(0xffffffffu, v, 16);
    v += __shfl_xor_sync(0xffffffffu, v, 8);
    v += __shfl_xor_sync(0xffffffffu, v, 4);
    v += __shfl_xor_sync(0xffffffffu, v, 2);
    v += __shfl_xor_sync(0xffffffffu, v, 1);
    return v;
}

// ---------------------------------------------------------------------------
// Warp-tiled 128x128x128 tf32 GEMM: D = Act @ W  (W^T rows in sWgt).
// ---------------------------------------------------------------------------
__device__ __forceinline__ void mma_gemm(const float* __restrict__ sAct,
                                         const float* __restrict__ sWgt,
                                         int mrow, int ncol, int gid, int tig,
                                         float acc[2][4][4])
{
    #pragma unroll
    for (int mt = 0; mt < 2; ++mt)
        #pragma unroll
        for (int nt = 0; nt < 4; ++nt)
            #pragma unroll
            for (int q = 0; q < 4; ++q) acc[mt][nt][q] = 0.f;

    #pragma unroll 2
    for (int k0 = 0; k0 < DDIM; k0 += 8) {
        uint32_t a[2][4], bf[4][2];
        #pragma unroll
        for (int mt = 0; mt < 2; ++mt) {
            const float* base = sAct + (mrow + mt * 16 + gid) * AP + k0 + tig;
            a[mt][0] = rna_tf32(base[0]);
            a[mt][1] = rna_tf32(base[8 * AP]);
            a[mt][2] = rna_tf32(base[4]);
            a[mt][3] = rna_tf32(base[8 * AP + 4]);
        }
        #pragma unroll
        for (int nt = 0; nt < 4; ++nt) {
            const float* base = sWgt + (ncol + nt * 8 + gid) * AP + k0 + tig;
            bf[nt][0] = __float_as_uint(base[0]);   // pre-rounded
            bf[nt][1] = __float_as_uint(base[4]);
        }
        #pragma unroll
        for (int mt = 0; mt < 2; ++mt)
            #pragma unroll
            for (int nt = 0; nt < 4; ++nt)
                mma8(acc[mt][nt], a[mt], bf[nt]);
    }
}

// ---------------------------------------------------------------------------
// Prep: blocks [0,512) K projection; [512,516) weight transpose;
//       [516,772) tf32-rounded copy of batch_input -> g_bi
// ---------------------------------------------------------------------------
__global__ __launch_bounds__(256) void prep_kernel(
    const float* __restrict__ bi, const float* __restrict__ kW,
    const float* __restrict__ kb,
    const float* __restrict__ hW, const float* __restrict__ qW,
    const float* __restrict__ gW, const float* __restrict__ s1W)
{
    extern __shared__ float sm1[];
    const int bx = blockIdx.x;
    const int t  = threadIdx.x;

    if (bx >= BB * RDIM + 4) {     // bi copy (tf32 round)
        const int w = bx - (BB * RDIM + 4);
        const float* src = bi + (size_t)w * 4096;
        float* dst = g_bi + (size_t)w * 4096;
        for (int i = t; i < 4096; i += 256)
            dst[i] = __uint_as_float(rna_tf32(src[i]));
        return;
    }
    if (bx >= BB * RDIM) {          // weight transpose
        const int w = bx - BB * RDIM;
        const float* W = (w == 0) ? hW : (w == 1) ? qW : (w == 2) ? gW : s1W;
        float* tile = sm1;          // 128*129
        for (int i = t; i < DDIM * DDIM; i += 256) {
            int k = i >> 7, n = i & 127;
            tile[k * 129 + n] = W[i];
        }
        __syncthreads();
        float* dst = g_wt + (size_t)w * DDIM * DDIM;
        for (int i = t; i < DDIM * DDIM; i += 256) {
            int n = i >> 7, k = i & 127;
            dst[i] = __uint_as_float(rna_tf32(tile[k * 129 + n]));
        }
        return;
    }

    float* sx = sm1;             // 16*128
    float* sw = sm1 + 2048;      // 128*128
    const int br = bx;

    const float4* src = (const float4*)(bi + (size_t)br * CDIM * DDIM);
    for (int i = t; i < (CDIM * DDIM) / 4; i += 256) ((float4*)sx)[i] = src[i];
    for (int i = t; i < (DDIM * DDIM) / 4; i += 256) ((float4*)sw)[i] = ((const float4*)kW)[i];
    __syncthreads();

    const int rw = t >> 4;
    const int j0 = (t & 15) * 8;

    float acc[8] = {0.f,0.f,0.f,0.f,0.f,0.f,0.f,0.f};
    #pragma unroll 4
    for (int k = 0; k < DDIM; ++k) {
        float a = sx[rw * DDIM + k];
        float4 w0 = *(const float4*)&sw[k * DDIM + j0];
        float4 w1 = *(const float4*)&sw[k * DDIM + j0 + 4];
        acc[0] += a * w0.x; acc[1] += a * w0.y; acc[2] += a * w0.z; acc[3] += a * w0.w;
        acc[4] += a * w1.x; acc[5] += a * w1.y; acc[6] += a * w1.z; acc[7] += a * w1.w;
    }
    float* dst = g_k + (size_t)br * CDIM * DDIM + rw * DDIM + j0;
    #pragma unroll
    for (int q = 0; q < 8; ++q)
        dst[q] = __uint_as_float(rna_tf32(acc[q] + kb[j0 + q]));
}

// ---------------------------------------------------------------------------
// Fused per-(batch, 8-pair) pipeline; all contractions on tensor pipe,
// P3/P5 operands staged through smem (coalesced LDG, conflict-free LDS).
// ---------------------------------------------------------------------------
__global__ __launch_bounds__(NT, 1) void phylo_kernel(
    const float* __restrict__ bi,   const float* __restrict__ seq_mask,
    const int*   __restrict__ rowA, const int*   __restrict__ colA,
    const float* __restrict__ hb,   const float* __restrict__ gb,
    const float* __restrict__ qb,   const float* __restrict__ s1b,
    const float* __restrict__ s2W,  const float* __restrict__ s2b,
    float* __restrict__ out)
{
    extern __shared__ __align__(16) float sm[];
    float* sW = sm;                    // 128*AP; also P3/P5 staging (idle G2->G3)
    float* sA = sW + 128 * AP;         // 128*AP
    float* sB = sA + 128 * AP;         // 128*AP
    __shared__ float salpha[PPB * RDIM];
    __shared__ float sred[4][RDIM][PPB];   // P3 K-slice partials (8KB)
    __shared__ int   srow[PPB], scol[PPB];

    const int t    = threadIdx.x;
    const int b    = blockIdx.y;
    const int pg0  = blockIdx.x * PPB;
    const int warp = t >> 5;
    const int lane = t & 31;
    const int gid  = lane >> 2;        // 0..7
    const int tig  = lane & 3;         // 0..3
    const int mrow = (warp >> 2) * 32;
    const int ncol = (warp & 3) * 32;

    if (t < PPB) { srow[t] = rowA[pg0 + t]; scol[t] = colA[pg0 + t]; }
    // stage hW^T
    for (int i = t; i < 4096; i += NT) {
        int n = i >> 5, k4 = i & 31;
        *(float4*)&sW[n * AP + k4 * 4] = ((const float4*)g_wt)[i];
    }
    __syncthreads();

    // sA = diff = x_i - x_j ; sB = x_j   (rows: p*16+c)
    for (int idx = t; idx < 4096; idx += NT) {
        int row = idx >> 5, d4 = idx & 31;
        int p = row >> 4, c = row & 15;
        const float4 xi = *((const float4*)(bi + (((size_t)b * RDIM + srow[p]) * CDIM + c) * DDIM) + d4);
        const float4 xj = *((const float4*)(bi + (((size_t)b * RDIM + scol[p]) * CDIM + c) * DDIM) + d4);
        *(float4*)&sA[row * AP + d4 * 4] = make_float4(xi.x - xj.x, xi.y - xj.y,
                                                       xi.z - xj.z, xi.w - xj.w);
        *(float4*)&sB[row * AP + d4 * 4] = xj;
    }
    __syncthreads();

    float acc[2][4][4];

    // ===== G1: h = diff @ hW + hb ; x = xj + sigmoid(h)*diff -> sB ==========
    mma_gemm(sA, sW, mrow, ncol, gid, tig, acc);
    #pragma unroll
    for (int nt = 0; nt < 4; ++nt) {
        int cc = ncol + nt * 8 + 2 * tig;
        float2 bb = *(const float2*)&hb[cc];
        #pragma unroll
        for (int mt = 0; mt < 2; ++mt) {
            #pragma unroll
            for (int h = 0; h < 2; ++h) {
                int row = mrow + mt * 16 + gid + 8 * h;
                float2 dv = *(float2*)&sA[row * AP + cc];
                float2 xv = *(float2*)&sB[row * AP + cc];
                float h0 = acc[mt][nt][2*h]   + bb.x;
                float h1 = acc[mt][nt][2*h+1] + bb.y;
                float z0 = 1.f / (1.f + __expf(-h0));
                float z1 = 1.f / (1.f + __expf(-h1));
                *(float2*)&sB[row * AP + cc] =
                    make_float2(xv.x + z0 * dv.x, xv.y + z1 * dv.y);
            }
        }
    }
    __syncthreads();
    for (int i = t; i < 4096; i += NT) {
        int n = i >> 5, k4 = i & 31;
        *(float4*)&sW[n * AP + k4 * 4] = ((const float4*)(g_wt + DDIM * DDIM))[i];
    }
    __syncthreads();

    // ===== G2: q = x @ qW + qb -> sA (XOR-swizzled: col ^ (p<<2)) ===========
    mma_gemm(sB, sW, mrow, ncol, gid, tig, acc);
    #pragma unroll
    for (int nt = 0; nt < 4; ++nt) {
        int cc = ncol + nt * 8 + 2 * tig;
        float2 bb = *(const float2*)&qb[cc];
        #pragma unroll
        for (int mt = 0; mt < 2; ++mt) {
            #pragma unroll
            for (int h = 0; h < 2; ++h) {
                int row = mrow + mt * 16 + gid + 8 * h;
                int swz = ((row >> 4) & 7) << 2;
                sA[row * AP + ((cc)     ^ swz)] = acc[mt][nt][2*h]   + bb.x;
                sA[row * AP + ((cc + 1) ^ swz)] = acc[mt][nt][2*h+1] + bb.y;
            }
        }
    }
    __syncthreads();

    // ===== P3 (tensor, staged): alpha[r][p] = <k_r, q_p>, K=2048 ============
    {
        const int mtm = warp >> 2;     // r-tile (16 rows)
        const int kc  = warp & 3;      // K slice within chunk (64 floats)
        float pacc[4] = {0.f, 0.f, 0.f, 0.f};
        const int sw4 = gid << 2;

        for (int ch = 0; ch < 8; ++ch) {
            // stage g_k[b, 0:64, ch*256 : ch*256+256] -> sW [64][KP3]
            for (int idx = t; idx < 4096; idx += NT) {
                int r = idx >> 6, c4 = idx & 63;
                *(float4*)&sW[r * KP3 + c4 * 4] =
                    *(const float4*)&g_k[((size_t)b * RDIM + r) * 2048 + ch * 256 + c4 * 4];
            }
            __syncthreads();
            #pragma unroll
            for (int ks = 0; ks < 8; ++ks) {
                int kk = kc * 64 + ks * 8;
                uint32_t a[4], bq[2];
                const float* ab = sW + (mtm * 16 + gid) * KP3 + kk + tig;
                a[0] = __float_as_uint(ab[0]);
                a[1] = __float_as_uint(ab[8 * KP3]);
                a[2] = __float_as_uint(ab[4]);
                a[3] = __float_as_uint(ab[8 * KP3 + 4]);
                int Kg = ch * 256 + kk + tig;
                int c  = Kg >> 7, d = Kg & 127;
                int rq = (gid * 16 + c) * AP;
                bq[0] = rna_tf32(sA[rq + (d ^ sw4)]);
                bq[1] = rna_tf32(sA[rq + ((d + 4) ^ sw4)]);
                mma8(pacc, a, bq);
            }
            __syncthreads();
        }
        int r0 = mtm * 16 + gid;
        sred[kc][r0][2 * tig]         = pacc[0];
        sred[kc][r0][2 * tig + 1]     = pacc[1];
        sred[kc][r0 + 8][2 * tig]     = pacc[2];
        sred[kc][r0 + 8][2 * tig + 1] = pacc[3];
    }
    __syncthreads();
    {   // reduce 4 K-slices -> salpha[p*64 + r]
        int r = t >> 3, p = t & 7;
        salpha[p * 64 + r] = (sred[0][r][p] + sred[1][r][p]
                            + sred[2][r][p] + sred[3][r][p]) * SCALE;
    }
    __syncthreads();

    // ===== P4: masked softmax over r =========================================
    if (warp < 8) {
        int p  = warp;
        int rI = srow[p], cI = scol[p];
        float v0 = salpha[p * 64 + lane];
        float v1 = salpha[p * 64 + 32 + lane];
        if (lane == rI      || lane == cI)      v0 = -INFINITY;
        if (lane + 32 == rI || lane + 32 == cI) v1 = -INFINITY;
        float mx = fmaxf(v0, v1);
        #pragma unroll
        for (int off = 16; off > 0; off >>= 1)
            mx = fmaxf(mx, __shfl_xor_sync(0xffffffffu, mx, off));
        float e0 = __expf(v0 - mx), e1 = __expf(v1 - mx);
        float s = warp_sum(e0 + e1);
        float inv = 1.f / s;
        salpha[p * 64 + lane]      = e0 * inv;
        salpha[p * 64 + 32 + lane] = e1 * inv;
    }
    __syncthreads();

    // ===== P5 (tensor, staged): x_glob[cd][p] = sum_r bi[r,cd]*alpha[p][r] ==
    {
        const int c = warp;            // 16 warps <-> 16 c
        float pc5[8][4];
        #pragma unroll
        for (int mt = 0; mt < 8; ++mt)
            #pragma unroll
            for (int q = 0; q < 4; ++q) pc5[mt][q] = 0.f;

        for (int ch = 0; ch < 8; ++ch) {
            // stage g_bi[b, ch*8 : ch*8+8, :, :] -> sW [8][KP5]
            for (int idx = t; idx < 4096; idx += NT) {
                int r8 = idx >> 9, c4 = idx & 511;
                *(float4*)&sW[r8 * KP5 + c4 * 4] =
                    *(const float4*)&g_bi[((size_t)b * RDIM + ch * 8 + r8) * 2048 + c4 * 4];
            }
            __syncthreads();
            uint32_t bq[2];
            bq[0] = rna_tf32(salpha[gid * 64 + ch * 8 + tig]);
            bq[1] = rna_tf32(salpha[gid * 64 + ch * 8 + tig + 4]);
            #pragma unroll
            for (int mt = 0; mt < 8; ++mt) {
                const float* ab = sW + tig * KP5 + c * 128 + mt * 16 + gid;
                uint32_t a[4];
                a[0] = __float_as_uint(ab[0]);
                a[1] = __float_as_uint(ab[8]);
                a[2] = __float_as_uint(ab[4 * KP5]);
                a[3] = __float_as_uint(ab[4 * KP5 + 8]);
                mma8(pc5[mt], a, bq);
            }
            __syncthreads();
        }
        #pragma unroll
        for (int mt = 0; mt < 8; ++mt) {
            int d = mt * 16 + gid;
            int p0 = 2 * tig, p1 = 2 * tig + 1;
            sA[(p0 * 16 + c) * AP + d]     = pc5[mt][0];
            sA[(p1 * 16 + c) * AP + d]     = pc5[mt][1];
            sA[(p0 * 16 + c) * AP + d + 8] = pc5[mt][2];
            sA[(p1 * 16 + c) * AP + d + 8] = pc5[mt][3];
        }
    }
    __syncthreads();
    for (int i = t; i < 4096; i += NT) {
        int n = i >> 5, k4 = i & 31;
        *(float4*)&sW[n * AP + k4 * 4] = ((const float4*)(g_wt + 2 * DDIM * DDIM))[i];
    }
    __syncthreads();

    // ===== G3: g = x_glob @ gW + gb ; x = x + sig(g)*(x_glob - x) -> sB =====
    mma_gemm(sA, sW, mrow, ncol, gid, tig, acc);
    #pragma unroll
    for (int nt = 0; nt < 4; ++nt) {
        int cc = ncol + nt * 8 + 2 * tig;
        float2 bb = *(const float2*)&gb[cc];
        #pragma unroll
        for (int mt = 0; mt < 2; ++mt) {
            #pragma unroll
            for (int h = 0; h < 2; ++h) {
                int row = mrow + mt * 16 + gid + 8 * h;
                float2 gv = *(float2*)&sA[row * AP + cc];
                float2 xv = *(float2*)&sB[row * AP + cc];
                float g0 = acc[mt][nt][2*h]   + bb.x;
                float g1 = acc[mt][nt][2*h+1] + bb.y;
                float w0 = 1.f / (1.f + __expf(-g0));
                float w1 = 1.f / (1.f + __expf(-g1));
                *(float2*)&sB[row * AP + cc] =
                    make_float2(xv.x + w0 * (gv.x - xv.x),
                                xv.y + w1 * (gv.y - xv.y));
            }
        }
    }
    __syncthreads();
    for (int i = t; i < 4096; i += NT) {
        int n = i >> 5, k4 = i & 31;
        *(float4*)&sW[n * AP + k4 * 4] = ((const float4*)(g_wt + 3 * DDIM * DDIM))[i];
    }
    __syncthreads();

    // ===== G4: u = gelu_exact(x @ s1W + s1b) -> sA ==========================
    mma_gemm(sB, sW, mrow, ncol, gid, tig, acc);
    const float is2 = 0.70710678118654752f;
    #pragma unroll
    for (int nt = 0; nt < 4; ++nt) {
        int cc = ncol + nt * 8 + 2 * tig;
        float2 bb = *(const float2*)&s1b[cc];
        #pragma unroll
        for (int mt = 0; mt < 2; ++mt) {
            #pragma unroll
            for (int h = 0; h < 2; ++h) {
                int row = mrow + mt * 16 + gid + 8 * h;
                float u0 = acc[mt][nt][2*h]   + bb.x;
                float u1 = acc[mt][nt][2*h+1] + bb.y;
                *(float2*)&sA[row * AP + cc] =
                    make_float2(0.5f * u0 * (1.f + erff(u0 * is2)),
                                0.5f * u1 * (1.f + erff(u1 * is2)));
            }
        }
    }
    __syncthreads();

    // ===== P8: s = u @ s2W + s2b ; masked row-sum ===========================
    if (warp < 8) {
        int p = warp;
        float4 w2 = *(const float4*)&s2W[lane * 4];
        float s2b0 = s2b[0];
        float total = 0.f;
        #pragma unroll
        for (int c = 0; c < CDIM; ++c) {
            float4 u4 = *(const float4*)&sA[(p * 16 + c) * AP + lane * 4];
            float part = u4.x * w2.x + u4.y * w2.y + u4.z * w2.z + u4.w * w2.w;
            part = warp_sum(part);
            total += (part + s2b0) * seq_mask[b * CDIM + c];
        }
        if (lane == 0) out[b * NPAIR + pg0 + p] = total;
    }
}

// ---------------------------------------------------------------------------
extern "C" void kernel_launch(void* const* d_in, const int* in_sizes, int n_in,
                              void* d_out, int out_size)
{
    (void)in_sizes; (void)n_in; (void)out_size;
    const float* bi       = (const float*)d_in[0];
    const float* seq_mask = (const float*)d_in[1];
    const int*   rowA     = (const int*)  d_in[2];
    const int*   colA     = (const int*)  d_in[3];
    const float* hW  = (const float*)d_in[4];
    const float* hb  = (const float*)d_in[5];
    const float* gW  = (const float*)d_in[6];
    const float* gb  = (const float*)d_in[7];
    const float* qW  = (const float*)d_in[8];
    const float* qb  = (const float*)d_in[9];
    const float* kW  = (const float*)d_in[10];
    const float* kb  = (const float*)d_in[11];
    const float* s1W = (const float*)d_in[12];
    const float* s1b = (const float*)d_in[13];
    const float* s2W = (const float*)d_in[14];
    const float* s2b = (const float*)d_in[15];
    float* out = (float*)d_out;

    const size_t psmem = (2048 + 16384) * sizeof(float);     // 72KB
    const size_t msmem = 3 * 128 * AP * sizeof(float);       // ~198KB

    cudaFuncSetAttribute(prep_kernel,  cudaFuncAttributeMaxDynamicSharedMemorySize, (int)psmem);
    cudaFuncSetAttribute(phylo_kernel, cudaFuncAttributeMaxDynamicSharedMemorySize, (int)msmem);

    prep_kernel<<<BB * RDIM + 4 + 256, 256, psmem>>>(bi, kW, kb, hW, qW, gW, s1W);
    phylo_kernel<<<dim3(NGRP, BB), NT, msmem>>>(
        bi, seq_mask, rowA, colA,
        hb, gb, qb, s1b, s2W, s2b, out);
}

// round 11
// speedup vs baseline: 1.4300x; 1.4300x over previous
#include <cuda_runtime.h>
#include <math.h>
#include <stdint.h>
#include <string.h>

#define BB     8
#define RDIM   64
#define CDIM   16
#define DDIM   128
#define NPAIR  2016
#define PPB    8
#define NGRP   (NPAIR / PPB)   // 252
#define NT     512
#define AP     132             // padded pitch (floats)

// scale = 1/sqrt(D*C) = 1/sqrt(2048)
#define SCALE  0.022097086912079608f

__device__ float g_k [BB * RDIM * CDIM * DDIM];   // K projection, tf32-rounded (4MB)
__device__ float g_bi[BB * RDIM * CDIM * DDIM];   // batch_input, tf32-rounded (4MB)
__device__ float g_wt[4 * DDIM * DDIM];           // W^T tf32-rounded: hW,qW,gW,s1W

// ---------------------------------------------------------------------------
static __device__ __forceinline__ uint32_t rna_tf32(float v) {
    uint32_t r;
    asm("cvt.rna.tf32.f32 %0, %1;" : "=r"(r) : "f"(v));
    return r;
}

static __device__ __forceinline__ void mma8(float c[4], const uint32_t a[4],
                                            const uint32_t b[2]) {
    asm volatile(
        "mma.sync.aligned.m16n8k8.row.col.f32.tf32.tf32.f32 "
        "{%0,%1,%2,%3}, {%4,%5,%6,%7}, {%8,%9}, {%0,%1,%2,%3};"
        : "+f"(c[0]), "+f"(c[1]), "+f"(c[2]), "+f"(c[3])
        : "r"(a[0]), "r"(a[1]), "r"(a[2]), "r"(a[3]), "r"(b[0]), "r"(b[1]));
}

// packed fp32x2 FMA: c(2xf32) += a * b   (PTX ISA 8.6, sm_100+, non-'a')
#define FMA2(c, a, b) \
    asm("fma.rn.f32x2 %0, %1, %2, %0;" : "+l"(c) : "l"(a), "l"(b))

__device__ __forceinline__ float warp_sum(float v) {
    v += __shfl_xor_sync(0xffffffffu, v, 16);
    v += __shfl_xor_sync(0xffffffffu, v, 8);
    v += __shfl_xor_sync(0xffffffffu, v, 4);
    v += __shfl_xor_sync(0xffffffffu, v, 2);
    v += __shfl_xor_sync(0xffffffffu, v, 1);
    return v;
}

// ---------------------------------------------------------------------------
// Warp-tiled 128x128x128 tf32 GEMM: D = Act @ W  (W^T rows in sWgt).
// ---------------------------------------------------------------------------
__device__ __forceinline__ void mma_gemm(const float* __restrict__ sAct,
                                         const float* __restrict__ sWgt,
                                         int mrow, int ncol, int gid, int tig,
                                         float acc[2][4][4])
{
    #pragma unroll
    for (int mt = 0; mt < 2; ++mt)
        #pragma unroll
        for (int nt = 0; nt < 4; ++nt)
            #pragma unroll
            for (int q = 0; q < 4; ++q) acc[mt][nt][q] = 0.f;

    #pragma unroll 2
    for (int k0 = 0; k0 < DDIM; k0 += 8) {
        uint32_t a[2][4], bf[4][2];
        #pragma unroll
        for (int mt = 0; mt < 2; ++mt) {
            const float* base = sAct + (mrow + mt * 16 + gid) * AP + k0 + tig;
            a[mt][0] = rna_tf32(base[0]);
            a[mt][1] = rna_tf32(base[8 * AP]);
            a[mt][2] = rna_tf32(base[4]);
            a[mt][3] = rna_tf32(base[8 * AP + 4]);
        }
        #pragma unroll
        for (int nt = 0; nt < 4; ++nt) {
            const float* base = sWgt + (ncol + nt * 8 + gid) * AP + k0 + tig;
            bf[nt][0] = __float_as_uint(base[0]);   // pre-rounded
            bf[nt][1] = __float_as_uint(base[4]);
        }
        #pragma unroll
        for (int mt = 0; mt < 2; ++mt)
            #pragma unroll
            for (int nt = 0; nt < 4; ++nt)
                mma8(acc[mt][nt], a[mt], bf[nt]);
    }
}

// ---------------------------------------------------------------------------
// Prep: blocks [0,512) K projection; [512,516) weight transpose;
//       [516,772) tf32-rounded copy of batch_input -> g_bi
// ---------------------------------------------------------------------------
__global__ __launch_bounds__(256) void prep_kernel(
    const float* __restrict__ bi, const float* __restrict__ kW,
    const float* __restrict__ kb,
    const float* __restrict__ hW, const float* __restrict__ qW,
    const float* __restrict__ gW, const float* __restrict__ s1W)
{
    extern __shared__ float sm1[];
    const int bx = blockIdx.x;
    const int t  = threadIdx.x;

    if (bx >= BB * RDIM + 4) {     // bi copy (tf32 round)
        const int w = bx - (BB * RDIM + 4);
        const float* src = bi + (size_t)w * 4096;
        float* dst = g_bi + (size_t)w * 4096;
        for (int i = t; i < 4096; i += 256)
            dst[i] = __uint_as_float(rna_tf32(src[i]));
        return;
    }
    if (bx >= BB * RDIM) {          // weight transpose
        const int w = bx - BB * RDIM;
        const float* W = (w == 0) ? hW : (w == 1) ? qW : (w == 2) ? gW : s1W;
        float* tile = sm1;          // 128*129
        for (int i = t; i < DDIM * DDIM; i += 256) {
            int k = i >> 7, n = i & 127;
            tile[k * 129 + n] = W[i];
        }
        __syncthreads();
        float* dst = g_wt + (size_t)w * DDIM * DDIM;
        for (int i = t; i < DDIM * DDIM; i += 256) {
            int n = i >> 7, k = i & 127;
            dst[i] = __uint_as_float(rna_tf32(tile[k * 129 + n]));
        }
        return;
    }

    float* sx = sm1;             // 16*128
    float* sw = sm1 + 2048;      // 128*128
    const int br = bx;

    const float4* src = (const float4*)(bi + (size_t)br * CDIM * DDIM);
    for (int i = t; i < (CDIM * DDIM) / 4; i += 256) ((float4*)sx)[i] = src[i];
    for (int i = t; i < (DDIM * DDIM) / 4; i += 256) ((float4*)sw)[i] = ((const float4*)kW)[i];
    __syncthreads();

    const int rw = t >> 4;
    const int j0 = (t & 15) * 8;

    float acc[8] = {0.f,0.f,0.f,0.f,0.f,0.f,0.f,0.f};
    #pragma unroll 4
    for (int k = 0; k < DDIM; ++k) {
        float a = sx[rw * DDIM + k];
        float4 w0 = *(const float4*)&sw[k * DDIM + j0];
        float4 w1 = *(const float4*)&sw[k * DDIM + j0 + 4];
        acc[0] += a * w0.x; acc[1] += a * w0.y; acc[2] += a * w0.z; acc[3] += a * w0.w;
        acc[4] += a * w1.x; acc[5] += a * w1.y; acc[6] += a * w1.z; acc[7] += a * w1.w;
    }
    float* dst = g_k + (size_t)br * CDIM * DDIM + rw * DDIM + j0;
    #pragma unroll
    for (int q = 0; q < 8; ++q)
        dst[q] = __uint_as_float(rna_tf32(acc[q] + kb[j0 + q]));
}

// ---------------------------------------------------------------------------
// Fused per-(batch, 8-pair) pipeline.
// GEMMs: tf32 mma.sync. P3: packed fp32x2 FFMA (exact fp32). P5: tf32 mma.
// ---------------------------------------------------------------------------
__global__ __launch_bounds__(NT, 1) void phylo_kernel(
    const float* __restrict__ bi,   const float* __restrict__ seq_mask,
    const int*   __restrict__ rowA, const int*   __restrict__ colA,
    const float* __restrict__ hb,   const float* __restrict__ gb,
    const float* __restrict__ qb,   const float* __restrict__ s1b,
    const float* __restrict__ s2W,  const float* __restrict__ s2b,
    float* __restrict__ out)
{
    extern __shared__ __align__(16) float sm[];
    float* sW = sm;                    // 128*AP  (W^T staged, tf32-rounded)
    float* sA = sW + 128 * AP;         // 128*AP
    float* sB = sA + 128 * AP;         // 128*AP
    __shared__ float salpha[PPB * RDIM];
    __shared__ int   srow[PPB], scol[PPB];

    const int t    = threadIdx.x;
    const int b    = blockIdx.y;
    const int pg0  = blockIdx.x * PPB;
    const int warp = t >> 5;
    const int lane = t & 31;
    const int gid  = lane >> 2;        // 0..7
    const int tig  = lane & 3;         // 0..3
    const int mrow = (warp >> 2) * 32;
    const int ncol = (warp & 3) * 32;

    if (t < PPB) { srow[t] = rowA[pg0 + t]; scol[t] = colA[pg0 + t]; }
    // stage hW^T
    for (int i = t; i < 4096; i += NT) {
        int n = i >> 5, k4 = i & 31;
        *(float4*)&sW[n * AP + k4 * 4] = ((const float4*)g_wt)[i];
    }
    __syncthreads();

    // sA = diff = x_i - x_j ; sB = x_j   (rows: p*16+c)
    for (int idx = t; idx < 4096; idx += NT) {
        int row = idx >> 5, d4 = idx & 31;
        int p = row >> 4, c = row & 15;
        const float4 xi = *((const float4*)(bi + (((size_t)b * RDIM + srow[p]) * CDIM + c) * DDIM) + d4);
        const float4 xj = *((const float4*)(bi + (((size_t)b * RDIM + scol[p]) * CDIM + c) * DDIM) + d4);
        *(float4*)&sA[row * AP + d4 * 4] = make_float4(xi.x - xj.x, xi.y - xj.y,
                                                       xi.z - xj.z, xi.w - xj.w);
        *(float4*)&sB[row * AP + d4 * 4] = xj;
    }
    __syncthreads();

    float acc[2][4][4];

    // ===== G1: h = diff @ hW + hb ; x = xj + sigmoid(h)*diff -> sB ==========
    mma_gemm(sA, sW, mrow, ncol, gid, tig, acc);
    #pragma unroll
    for (int nt = 0; nt < 4; ++nt) {
        int cc = ncol + nt * 8 + 2 * tig;
        float2 bb = *(const float2*)&hb[cc];
        #pragma unroll
        for (int mt = 0; mt < 2; ++mt) {
            #pragma unroll
            for (int h = 0; h < 2; ++h) {
                int row = mrow + mt * 16 + gid + 8 * h;
                float2 dv = *(float2*)&sA[row * AP + cc];
                float2 xv = *(float2*)&sB[row * AP + cc];
                float h0 = acc[mt][nt][2*h]   + bb.x;
                float h1 = acc[mt][nt][2*h+1] + bb.y;
                float z0 = 1.f / (1.f + __expf(-h0));
                float z1 = 1.f / (1.f + __expf(-h1));
                *(float2*)&sB[row * AP + cc] =
                    make_float2(xv.x + z0 * dv.x, xv.y + z1 * dv.y);
            }
        }
    }
    __syncthreads();
    for (int i = t; i < 4096; i += NT) {
        int n = i >> 5, k4 = i & 31;
        *(float4*)&sW[n * AP + k4 * 4] = ((const float4*)(g_wt + DDIM * DDIM))[i];
    }
    __syncthreads();

    // ===== G2: q = x @ qW + qb -> sA ========================================
    mma_gemm(sB, sW, mrow, ncol, gid, tig, acc);
    #pragma unroll
    for (int nt = 0; nt < 4; ++nt) {
        int cc = ncol + nt * 8 + 2 * tig;
        float2 bb = *(const float2*)&qb[cc];
        #pragma unroll
        for (int mt = 0; mt < 2; ++mt) {
            #pragma unroll
            for (int h = 0; h < 2; ++h) {
                int row = mrow + mt * 16 + gid + 8 * h;
                *(float2*)&sA[row * AP + cc] =
                    make_float2(acc[mt][nt][2*h] + bb.x, acc[mt][nt][2*h+1] + bb.y);
            }
        }
    }
    __syncthreads();

    // ===== P3 (packed fp32x2): alpha[p][r] = scale * <q_p, k_r> =============
    // warp handles r0..r0+3; p split in two halves of 4 to bound registers.
    {
        const int r0 = warp * 4;
        const int d0 = lane * 4;
        #pragma unroll
        for (int half = 0; half < 2; ++half) {
            unsigned long long pacc[4][4];
            #pragma unroll
            for (int p4 = 0; p4 < 4; ++p4)
                #pragma unroll
                for (int rr = 0; rr < 4; ++rr) pacc[p4][rr] = 0ull;

            #pragma unroll 2
            for (int c = 0; c < CDIM; ++c) {
                unsigned long long kxy[4], kzw[4], qxy[4], qzw[4];
                #pragma unroll
                for (int rr = 0; rr < 4; ++rr) {
                    const float* kp = &g_k[(((size_t)b * RDIM + r0 + rr) * CDIM + c) * DDIM + d0];
                    kxy[rr] = *(const unsigned long long*)(kp);
                    kzw[rr] = *(const unsigned long long*)(kp + 2);
                }
                #pragma unroll
                for (int p4 = 0; p4 < 4; ++p4) {
                    const float* qp = &sA[((half * 4 + p4) * 16 + c) * AP + d0];
                    qxy[p4] = *(const unsigned long long*)(qp);
                    qzw[p4] = *(const unsigned long long*)(qp + 2);
                }
                #pragma unroll
                for (int p4 = 0; p4 < 4; ++p4)
                    #pragma unroll
                    for (int rr = 0; rr < 4; ++rr) {
                        FMA2(pacc[p4][rr], qxy[p4], kxy[rr]);
                        FMA2(pacc[p4][rr], qzw[p4], kzw[rr]);
                    }
            }
            #pragma unroll
            for (int p4 = 0; p4 < 4; ++p4)
                #pragma unroll
                for (int rr = 0; rr < 4; ++rr) {
                    float2 f;
                    memcpy(&f, &pacc[p4][rr], 8);
                    float v = warp_sum(f.x + f.y);
                    if (lane == 0)
                        salpha[(half * 4 + p4) * 64 + r0 + rr] = v * SCALE;
                }
        }
    }
    __syncthreads();

    // ===== P4: masked softmax over r =========================================
    if (warp < 8) {
        int p  = warp;
        int rI = srow[p], cI = scol[p];
        float v0 = salpha[p * 64 + lane];
        float v1 = salpha[p * 64 + 32 + lane];
        if (lane == rI      || lane == cI)      v0 = -INFINITY;
        if (lane + 32 == rI || lane + 32 == cI) v1 = -INFINITY;
        float mx = fmaxf(v0, v1);
        #pragma unroll
        for (int off = 16; off > 0; off >>= 1)
            mx = fmaxf(mx, __shfl_xor_sync(0xffffffffu, mx, off));
        float e0 = __expf(v0 - mx), e1 = __expf(v1 - mx);
        float s = warp_sum(e0 + e1);
        float inv = 1.f / s;
        salpha[p * 64 + lane]      = e0 * inv;
        salpha[p * 64 + 32 + lane] = e1 * inv;
    }
    __syncthreads();

    // ===== P5 (tensor): x_glob[d][p] per c = sum_r bi[r,c,d]*alpha[p][r] ====
    {
        const int c = warp;            // 16 warps <-> 16 c
        float pc5[8][4];
        #pragma unroll
        for (int mt = 0; mt < 8; ++mt)
            #pragma unroll
            for (int q = 0; q < 4; ++q) pc5[mt][q] = 0.f;

        const float* abase = g_bi + ((size_t)b * RDIM * CDIM + c) * DDIM;
        #pragma unroll
        for (int ks = 0; ks < 8; ++ks) {
            int r = ks * 8 + tig;
            uint32_t bq[2];
            bq[0] = rna_tf32(salpha[gid * 64 + r]);
            bq[1] = rna_tf32(salpha[gid * 64 + r + 4]);
            #pragma unroll
            for (int mt = 0; mt < 8; ++mt) {
                const float* ab = abase + (size_t)r * (CDIM * DDIM) + mt * 16 + gid;
                uint32_t a[4];
                a[0] = __float_as_uint(ab[0]);
                a[1] = __float_as_uint(ab[8]);
                a[2] = __float_as_uint(ab[4 * CDIM * DDIM]);
                a[3] = __float_as_uint(ab[4 * CDIM * DDIM + 8]);
                mma8(pc5[mt], a, bq);
            }
        }
        #pragma unroll
        for (int mt = 0; mt < 8; ++mt) {
            int d = mt * 16 + gid;
            int p0 = 2 * tig, p1 = 2 * tig + 1;
            sA[(p0 * 16 + c) * AP + d]     = pc5[mt][0];
            sA[(p1 * 16 + c) * AP + d]     = pc5[mt][1];
            sA[(p0 * 16 + c) * AP + d + 8] = pc5[mt][2];
            sA[(p1 * 16 + c) * AP + d + 8] = pc5[mt][3];
        }
    }
    __syncthreads();
    for (int i = t; i < 4096; i += NT) {
        int n = i >> 5, k4 = i & 31;
        *(float4*)&sW[n * AP + k4 * 4] = ((const float4*)(g_wt + 2 * DDIM * DDIM))[i];
    }
    __syncthreads();

    // ===== G3: g = x_glob @ gW + gb ; x = x + sig(g)*(x_glob - x) -> sB =====
    mma_gemm(sA, sW, mrow, ncol, gid, tig, acc);
    #pragma unroll
    for (int nt = 0; nt < 4; ++nt) {
        int cc = ncol + nt * 8 + 2 * tig;
        float2 bb = *(const float2*)&gb[cc];
        #pragma unroll
        for (int mt = 0; mt < 2; ++mt) {
            #pragma unroll
            for (int h = 0; h < 2; ++h) {
                int row = mrow + mt * 16 + gid + 8 * h;
                float2 gv = *(float2*)&sA[row * AP + cc];
                float2 xv = *(float2*)&sB[row * AP + cc];
                float g0 = acc[mt][nt][2*h]   + bb.x;
                float g1 = acc[mt][nt][2*h+1] + bb.y;
                float w0 = 1.f / (1.f + __expf(-g0));
                float w1 = 1.f / (1.f + __expf(-g1));
                *(float2*)&sB[row * AP + cc] =
                    make_float2(xv.x + w0 * (gv.x - xv.x),
                                xv.y + w1 * (gv.y - xv.y));
            }
        }
    }
    __syncthreads();
    for (int i = t; i < 4096; i += NT) {
        int n = i >> 5, k4 = i & 31;
        *(float4*)&sW[n * AP + k4 * 4] = ((const float4*)(g_wt + 3 * DDIM * DDIM))[i];
    }
    __syncthreads();

    // ===== G4: u = gelu_exact(x @ s1W + s1b) -> sA ==========================
    mma_gemm(sB, sW, mrow, ncol, gid, tig, acc);
    const float is2 = 0.70710678118654752f;
    #pragma unroll
    for (int nt = 0; nt < 4; ++nt) {
        int cc = ncol + nt * 8 + 2 * tig;
        float2 bb = *(const float2*)&s1b[cc];
        #pragma unroll
        for (int mt = 0; mt < 2; ++mt) {
            #pragma unroll
            for (int h = 0; h < 2; ++h) {
                int row = mrow + mt * 16 + gid + 8 * h;
                float u0 = acc[mt][nt][2*h]   + bb.x;
                float u1 = acc[mt][nt][2*h+1] + bb.y;
                *(float2*)&sA[row * AP + cc] =
                    make_float2(0.5f * u0 * (1.f + erff(u0 * is2)),
                                0.5f * u1 * (1.f + erff(u1 * is2)));
            }
        }
    }
    __syncthreads();

    // ===== P8: s = u @ s2W + s2b ; masked row-sum ===========================
    if (warp < 8) {
        int p = warp;
        float4 w2 = *(const float4*)&s2W[lane * 4];
        float s2b0 = s2b[0];
        float total = 0.f;
        #pragma unroll
        for (int c = 0; c < CDIM; ++c) {
            float4 u4 = *(const float4*)&sA[(p * 16 + c) * AP + lane * 4];
            float part = u4.x * w2.x + u4.y * w2.y + u4.z * w2.z + u4.w * w2.w;
            part = warp_sum(part);
            total += (part + s2b0) * seq_mask[b * CDIM + c];
        }
        if (lane == 0) out[b * NPAIR + pg0 + p] = total;
    }
}

// ---------------------------------------------------------------------------
extern "C" void kernel_launch(void* const* d_in, const int* in_sizes, int n_in,
                              void* d_out, int out_size)
{
    (void)in_sizes; (void)n_in; (void)out_size;
    const float* bi       = (const float*)d_in[0];
    const float* seq_mask = (const float*)d_in[1];
    const int*   rowA     = (const int*)  d_in[2];
    const int*   colA     = (const int*)  d_in[3];
    const float* hW  = (const float*)d_in[4];
    const float* hb  = (const float*)d_in[5];
    const float* gW  = (const float*)d_in[6];
    const float* gb  = (const float*)d_in[7];
    const float* qW  = (const float*)d_in[8];
    const float* qb  = (const float*)d_in[9];
    const float* kW  = (const float*)d_in[10];
    const float* kb  = (const float*)d_in[11];
    const float* s1W = (const float*)d_in[12];
    const float* s1b = (const float*)d_in[13];
    const float* s2W = (const float*)d_in[14];
    const float* s2b = (const float*)d_in[15];
    float* out = (float*)d_out;

    const size_t psmem = (2048 + 16384) * sizeof(float);     // 72KB
    const size_t msmem = 3 * 128 * AP * sizeof(float);       // ~198KB

    cudaFuncSetAttribute(prep_kernel,  cudaFuncAttributeMaxDynamicSharedMemorySize, (int)psmem);
    cudaFuncSetAttribute(phylo_kernel, cudaFuncAttributeMaxDynamicSharedMemorySize, (int)msmem);

    prep_kernel<<<BB * RDIM + 4 + 256, 256, psmem>>>(bi, kW, kb, hW, qW, gW, s1W);
    phylo_kernel<<<dim3(NGRP, BB), NT, msmem>>>(
        bi, seq_mask, rowA, colA,
        hb, gb, qb, s1b, s2W, s2b, out);
}

// round 12
// speedup vs baseline: 1.4817x; 1.0362x over previous
#include <cuda_runtime.h>
#include <math.h>
#include <stdint.h>
#include <string.h>

#define BB     8
#define RDIM   64
#define CDIM   16
#define DDIM   128
#define NPAIR  2016
#define PPB    4
#define NGRP   (NPAIR / PPB)   // 504
#define NT     256
#define AP     132             // padded pitch (floats)

// scale = 1/sqrt(D*C) = 1/sqrt(2048)
#define SCALE  0.022097086912079608f

__device__ float g_k  [BB * RDIM * CDIM * DDIM];  // K projection, tf32-rounded (4MB)
__device__ float g_bi [BB * RDIM * CDIM * DDIM];  // batch_input, tf32-rounded (4MB)
// fragment-ordered W^T, tf32-rounded: [w][k0/8][n][frag8]; frag idx = 2*(k&3)+((k&7)>>2)
__device__ float g_wtf[4 * DDIM * DDIM];

// ---------------------------------------------------------------------------
static __device__ __forceinline__ uint32_t rna_tf32(float v) {
    uint32_t r;
    asm("cvt.rna.tf32.f32 %0, %1;" : "=r"(r) : "f"(v));
    return r;
}

static __device__ __forceinline__ void mma8(float c[4], const uint32_t a[4],
                                            const uint32_t b[2]) {
    asm volatile(
        "mma.sync.aligned.m16n8k8.row.col.f32.tf32.tf32.f32 "
        "{%0,%1,%2,%3}, {%4,%5,%6,%7}, {%8,%9}, {%0,%1,%2,%3};"
        : "+f"(c[0]), "+f"(c[1]), "+f"(c[2]), "+f"(c[3])
        : "r"(a[0]), "r"(a[1]), "r"(a[2]), "r"(a[3]), "r"(b[0]), "r"(b[1]));
}

// packed fp32x2 FMA: c(2xf32) += a * b
#define FMA2(c, a, b) \
    asm("fma.rn.f32x2 %0, %1, %2, %0;" : "+l"(c) : "l"(a), "l"(b))

__device__ __forceinline__ float warp_sum(float v) {
    v += __shfl_xor_sync(0xffffffffu, v, 16);
    v += __shfl_xor_sync(0xffffffffu, v, 8);
    v += __shfl_xor_sync(0xffffffffu, v, 4);
    v += __shfl_xor_sync(0xffffffffu, v, 2);
    v += __shfl_xor_sync(0xffffffffu, v, 1);
    return v;
}

// ---------------------------------------------------------------------------
// Warp-tiled 64x128x128 tf32 GEMM: D = Act(64xK) @ W; B-frags via coalesced
// LDG.64 from fragment-ordered g_wtf (L1-hot). 8 warps: 2 mrow x 4 ncol tiles.
// ---------------------------------------------------------------------------
__device__ __forceinline__ void mma_gemm(const float* __restrict__ sAct,
                                         int widx,
                                         int mrow, int ncol, int gid, int tig,
                                         float acc[2][4][4])
{
    #pragma unroll
    for (int mt = 0; mt < 2; ++mt)
        #pragma unroll
        for (int nt = 0; nt < 4; ++nt)
            #pragma unroll
            for (int q = 0; q < 4; ++q) acc[mt][nt][q] = 0.f;

    const uint2* wb = (const uint2*)(g_wtf + (size_t)widx * DDIM * DDIM);

    #pragma unroll 2
    for (int k0g = 0; k0g < 16; ++k0g) {
        uint32_t a[2][4], bf[4][2];
        #pragma unroll
        for (int mt = 0; mt < 2; ++mt) {
            const float* base = sAct + (mrow + mt * 16 + gid) * AP + k0g * 8 + tig;
            a[mt][0] = rna_tf32(base[0]);
            a[mt][1] = rna_tf32(base[8 * AP]);
            a[mt][2] = rna_tf32(base[4]);
            a[mt][3] = rna_tf32(base[8 * AP + 4]);
        }
        #pragma unroll
        for (int nt = 0; nt < 4; ++nt) {
            uint2 bv = wb[(k0g * DDIM + ncol + nt * 8 + gid) * 4 + tig];
            bf[nt][0] = bv.x;
            bf[nt][1] = bv.y;
        }
        #pragma unroll
        for (int mt = 0; mt < 2; ++mt)
            #pragma unroll
            for (int nt = 0; nt < 4; ++nt)
                mma8(acc[mt][nt], a[mt], bf[nt]);
    }
}

// ---------------------------------------------------------------------------
// Prep: [0,512) K projection; [512,516) weight -> fragment order; [516,772) bi
// ---------------------------------------------------------------------------
__global__ __launch_bounds__(256) void prep_kernel(
    const float* __restrict__ bi, const float* __restrict__ kW,
    const float* __restrict__ kb,
    const float* __restrict__ hW, const float* __restrict__ qW,
    const float* __restrict__ gW, const float* __restrict__ s1W)
{
    extern __shared__ float sm1[];
    const int bx = blockIdx.x;
    const int t  = threadIdx.x;

    if (bx >= BB * RDIM + 4) {     // bi copy (tf32 round)
        const int w = bx - (BB * RDIM + 4);
        const float* src = bi + (size_t)w * 4096;
        float* dst = g_bi + (size_t)w * 4096;
        for (int i = t; i < 4096; i += 256)
            dst[i] = __uint_as_float(rna_tf32(src[i]));
        return;
    }
    if (bx >= BB * RDIM) {          // weight -> fragment-ordered g_wtf
        const int w = bx - BB * RDIM;
        const float* W = (w == 0) ? hW : (w == 1) ? qW : (w == 2) ? gW : s1W;
        float* tile = sm1;          // 128*129, tile[k*129+n]
        for (int i = t; i < DDIM * DDIM; i += 256) {
            int k = i >> 7, n = i & 127;
            tile[k * 129 + n] = W[i];
        }
        __syncthreads();
        float* dst = g_wtf + (size_t)w * DDIM * DDIM;
        for (int i = t; i < DDIM * DDIM; i += 256) {
            // i = ((k0g*128)+n)*8 + f ; f = 2*tig + hi -> k = k0g*8 + hi*4 + tig
            int f   = i & 7;
            int n   = (i >> 3) & 127;
            int k0g = i >> 10;
            int k   = k0g * 8 + (f & 1) * 4 + (f >> 1);
            dst[i] = __uint_as_float(rna_tf32(tile[k * 129 + n]));
        }
        return;
    }

    float* sx = sm1;             // 16*128
    float* sw = sm1 + 2048;      // 128*128
    const int br = bx;

    const float4* src = (const float4*)(bi + (size_t)br * CDIM * DDIM);
    for (int i = t; i < (CDIM * DDIM) / 4; i += 256) ((float4*)sx)[i] = src[i];
    for (int i = t; i < (DDIM * DDIM) / 4; i += 256) ((float4*)sw)[i] = ((const float4*)kW)[i];
    __syncthreads();

    const int rw = t >> 4;
    const int j0 = (t & 15) * 8;

    float acc[8] = {0.f,0.f,0.f,0.f,0.f,0.f,0.f,0.f};
    #pragma unroll 4
    for (int k = 0; k < DDIM; ++k) {
        float a = sx[rw * DDIM + k];
        float4 w0 = *(const float4*)&sw[k * DDIM + j0];
        float4 w1 = *(const float4*)&sw[k * DDIM + j0 + 4];
        acc[0] += a * w0.x; acc[1] += a * w0.y; acc[2] += a * w0.z; acc[3] += a * w0.w;
        acc[4] += a * w1.x; acc[5] += a * w1.y; acc[6] += a * w1.z; acc[7] += a * w1.w;
    }
    float* dst = g_k + (size_t)br * CDIM * DDIM + rw * DDIM + j0;
    #pragma unroll
    for (int q = 0; q < 8; ++q)
        dst[q] = __uint_as_float(rna_tf32(acc[q] + kb[j0 + q]));
}

// ---------------------------------------------------------------------------
// Fused per-(batch, 4-pair) pipeline. 256 threads, 2 CTAs/SM.
// ---------------------------------------------------------------------------
__global__ __launch_bounds__(NT, 2) void phylo_kernel(
    const float* __restrict__ bi,   const float* __restrict__ seq_mask,
    const int*   __restrict__ rowA, const int*   __restrict__ colA,
    const float* __restrict__ hb,   const float* __restrict__ gb,
    const float* __restrict__ qb,   const float* __restrict__ s1b,
    const float* __restrict__ s2W,  const float* __restrict__ s2b,
    float* __restrict__ out)
{
    extern __shared__ __align__(16) float sm[];
    float* sA = sm;                    // 64*AP
    float* sB = sA + 64 * AP;          // 64*AP
    __shared__ float salpha[PPB * RDIM];
    __shared__ int   srow[PPB], scol[PPB];

    const int t    = threadIdx.x;
    const int b    = blockIdx.y;
    const int pg0  = blockIdx.x * PPB;
    const int warp = t >> 5;           // 0..7
    const int lane = t & 31;
    const int gid  = lane >> 2;        // 0..7
    const int tig  = lane & 3;         // 0..3
    const int mrow = (warp >> 2) * 32; // {0,32}
    const int ncol = (warp & 3) * 32;  // {0,32,64,96}

    if (t < PPB) { srow[t] = rowA[pg0 + t]; scol[t] = colA[pg0 + t]; }
    __syncthreads();

    // sA = diff = x_i - x_j ; sB = x_j   (rows: p*16+c, 64 rows)
    for (int idx = t; idx < 2048; idx += NT) {
        int row = idx >> 5, d4 = idx & 31;
        int p = row >> 4, c = row & 15;
        const float4 xi = *((const float4*)(bi + (((size_t)b * RDIM + srow[p]) * CDIM + c) * DDIM) + d4);
        const float4 xj = *((const float4*)(bi + (((size_t)b * RDIM + scol[p]) * CDIM + c) * DDIM) + d4);
        *(float4*)&sA[row * AP + d4 * 4] = make_float4(xi.x - xj.x, xi.y - xj.y,
                                                       xi.z - xj.z, xi.w - xj.w);
        *(float4*)&sB[row * AP + d4 * 4] = xj;
    }
    __syncthreads();

    float acc[2][4][4];

    // ===== G1: h = diff @ hW + hb ; x = xj + sigmoid(h)*diff -> sB ==========
    mma_gemm(sA, 0, mrow, ncol, gid, tig, acc);
    #pragma unroll
    for (int nt = 0; nt < 4; ++nt) {
        int cc = ncol + nt * 8 + 2 * tig;
        float2 bb = *(const float2*)&hb[cc];
        #pragma unroll
        for (int mt = 0; mt < 2; ++mt) {
            #pragma unroll
            for (int h = 0; h < 2; ++h) {
                int row = mrow + mt * 16 + gid + 8 * h;
                float2 dv = *(float2*)&sA[row * AP + cc];
                float2 xv = *(float2*)&sB[row * AP + cc];
                float h0 = acc[mt][nt][2*h]   + bb.x;
                float h1 = acc[mt][nt][2*h+1] + bb.y;
                float z0 = 1.f / (1.f + __expf(-h0));
                float z1 = 1.f / (1.f + __expf(-h1));
                *(float2*)&sB[row * AP + cc] =
                    make_float2(xv.x + z0 * dv.x, xv.y + z1 * dv.y);
            }
        }
    }
    __syncthreads();

    // ===== G2: q = x @ qW + qb -> sA ========================================
    mma_gemm(sB, 1, mrow, ncol, gid, tig, acc);
    #pragma unroll
    for (int nt = 0; nt < 4; ++nt) {
        int cc = ncol + nt * 8 + 2 * tig;
        float2 bb = *(const float2*)&qb[cc];
        #pragma unroll
        for (int mt = 0; mt < 2; ++mt) {
            #pragma unroll
            for (int h = 0; h < 2; ++h) {
                int row = mrow + mt * 16 + gid + 8 * h;
                *(float2*)&sA[row * AP + cc] =
                    make_float2(acc[mt][nt][2*h] + bb.x, acc[mt][nt][2*h+1] + bb.y);
            }
        }
    }
    __syncthreads();

    // ===== P3 (packed fp32x2): alpha[p][r] = scale * <q_p, k_r> =============
    // warp handles r = warp*8 .. +7 in two halves of 4; all 4 pairs.
    {
        const int r0 = warp * 8;
        const int d0 = lane * 4;
        #pragma unroll
        for (int half = 0; half < 2; ++half) {
            const int rh = r0 + half * 4;
            unsigned long long pacc[4][4];
            #pragma unroll
            for (int p4 = 0; p4 < 4; ++p4)
                #pragma unroll
                for (int rr = 0; rr < 4; ++rr) pacc[p4][rr] = 0ull;

            #pragma unroll 2
            for (int c = 0; c < CDIM; ++c) {
                unsigned long long kxy[4], kzw[4], qxy[4], qzw[4];
                #pragma unroll
                for (int rr = 0; rr < 4; ++rr) {
                    const float* kp = &g_k[(((size_t)b * RDIM + rh + rr) * CDIM + c) * DDIM + d0];
                    kxy[rr] = *(const unsigned long long*)(kp);
                    kzw[rr] = *(const unsigned long long*)(kp + 2);
                }
                #pragma unroll
                for (int p4 = 0; p4 < 4; ++p4) {
                    const float* qp = &sA[(p4 * 16 + c) * AP + d0];
                    qxy[p4] = *(const unsigned long long*)(qp);
                    qzw[p4] = *(const unsigned long long*)(qp + 2);
                }
                #pragma unroll
                for (int p4 = 0; p4 < 4; ++p4)
                    #pragma unroll
                    for (int rr = 0; rr < 4; ++rr) {
                        FMA2(pacc[p4][rr], qxy[p4], kxy[rr]);
                        FMA2(pacc[p4][rr], qzw[p4], kzw[rr]);
                    }
            }
            #pragma unroll
            for (int p4 = 0; p4 < 4; ++p4)
                #pragma unroll
                for (int rr = 0; rr < 4; ++rr) {
                    float2 f;
                    memcpy(&f, &pacc[p4][rr], 8);
                    float v = warp_sum(f.x + f.y);
                    if (lane == 0)
                        salpha[p4 * 64 + rh + rr] = v * SCALE;
                }
        }
    }
    __syncthreads();

    // ===== P4: masked softmax over r (4 warps) ===============================
    if (warp < PPB) {
        int p  = warp;
        int rI = srow[p], cI = scol[p];
        float v0 = salpha[p * 64 + lane];
        float v1 = salpha[p * 64 + 32 + lane];
        if (lane == rI      || lane == cI)      v0 = -INFINITY;
        if (lane + 32 == rI || lane + 32 == cI) v1 = -INFINITY;
        float mx = fmaxf(v0, v1);
        #pragma unroll
        for (int off = 16; off > 0; off >>= 1)
            mx = fmaxf(mx, __shfl_xor_sync(0xffffffffu, mx, off));
        float e0 = __expf(v0 - mx), e1 = __expf(v1 - mx);
        float s = warp_sum(e0 + e1);
        float inv = 1.f / s;
        salpha[p * 64 + lane]      = e0 * inv;
        salpha[p * 64 + 32 + lane] = e1 * inv;
    }
    __syncthreads();

    // ===== P5 (tensor): x_glob[d][p] per c = sum_r bi[r,c,d]*alpha[p][r] ====
    // 8 warps x 2 c-values each; b-cols p valid for gid<4.
    {
        #pragma unroll
        for (int ci = 0; ci < 2; ++ci) {
            const int c = warp + ci * 8;
            float pc5[8][4];
            #pragma unroll
            for (int mt = 0; mt < 8; ++mt)
                #pragma unroll
                for (int q = 0; q < 4; ++q) pc5[mt][q] = 0.f;

            const float* abase = g_bi + ((size_t)b * RDIM * CDIM + c) * DDIM;
            #pragma unroll
            for (int ks = 0; ks < 8; ++ks) {
                int r = ks * 8 + tig;
                uint32_t bq[2];
                bq[0] = (gid < PPB) ? rna_tf32(salpha[gid * 64 + r])     : 0u;
                bq[1] = (gid < PPB) ? rna_tf32(salpha[gid * 64 + r + 4]) : 0u;
                #pragma unroll
                for (int mt = 0; mt < 8; ++mt) {
                    const float* ab = abase + (size_t)r * (CDIM * DDIM) + mt * 16 + gid;
                    uint32_t a[4];
                    a[0] = __float_as_uint(ab[0]);
                    a[1] = __float_as_uint(ab[8]);
                    a[2] = __float_as_uint(ab[4 * CDIM * DDIM]);
                    a[3] = __float_as_uint(ab[4 * CDIM * DDIM + 8]);
                    mma8(pc5[mt], a, bq);
                }
            }
            int p0 = 2 * tig, p1 = 2 * tig + 1;
            #pragma unroll
            for (int mt = 0; mt < 8; ++mt) {
                int d = mt * 16 + gid;
                if (p0 < PPB) sA[(p0 * 16 + c) * AP + d]     = pc5[mt][0];
                if (p1 < PPB) sA[(p1 * 16 + c) * AP + d]     = pc5[mt][1];
                if (p0 < PPB) sA[(p0 * 16 + c) * AP + d + 8] = pc5[mt][2];
                if (p1 < PPB) sA[(p1 * 16 + c) * AP + d + 8] = pc5[mt][3];
            }
        }
    }
    __syncthreads();

    // ===== G3: g = x_glob @ gW + gb ; x = x + sig(g)*(x_glob - x) -> sB =====
    mma_gemm(sA, 2, mrow, ncol, gid, tig, acc);
    #pragma unroll
    for (int nt = 0; nt < 4; ++nt) {
        int cc = ncol + nt * 8 + 2 * tig;
        float2 bb = *(const float2*)&gb[cc];
        #pragma unroll
        for (int mt = 0; mt < 2; ++mt) {
            #pragma unroll
            for (int h = 0; h < 2; ++h) {
                int row = mrow + mt * 16 + gid + 8 * h;
                float2 gv = *(float2*)&sA[row * AP + cc];
                float2 xv = *(float2*)&sB[row * AP + cc];
                float g0 = acc[mt][nt][2*h]   + bb.x;
                float g1 = acc[mt][nt][2*h+1] + bb.y;
                float w0 = 1.f / (1.f + __expf(-g0));
                float w1 = 1.f / (1.f + __expf(-g1));
                *(float2*)&sB[row * AP + cc] =
                    make_float2(xv.x + w0 * (gv.x - xv.x),
                                xv.y + w1 * (gv.y - xv.y));
            }
        }
    }
    __syncthreads();

    // ===== G4: u = gelu_exact(x @ s1W + s1b) -> sA ==========================
    mma_gemm(sB, 3, mrow, ncol, gid, tig, acc);
    const float is2 = 0.70710678118654752f;
    #pragma unroll
    for (int nt = 0; nt < 4; ++nt) {
        int cc = ncol + nt * 8 + 2 * tig;
        float2 bb = *(const float2*)&s1b[cc];
        #pragma unroll
        for (int mt = 0; mt < 2; ++mt) {
            #pragma unroll
            for (int h = 0; h < 2; ++h) {
                int row = mrow + mt * 16 + gid + 8 * h;
                float u0 = acc[mt][nt][2*h]   + bb.x;
                float u1 = acc[mt][nt][2*h+1] + bb.y;
                *(float2*)&sA[row * AP + cc] =
                    make_float2(0.5f * u0 * (1.f + erff(u0 * is2)),
                                0.5f * u1 * (1.f + erff(u1 * is2)));
            }
        }
    }
    __syncthreads();

    // ===== P8: s = u @ s2W + s2b ; masked row-sum ===========================
    if (warp < PPB) {
        int p = warp;
        float4 w2 = *(const float4*)&s2W[lane * 4];
        float s2b0 = s2b[0];
        float total = 0.f;
        #pragma unroll
        for (int c = 0; c < CDIM; ++c) {
            float4 u4 = *(const float4*)&sA[(p * 16 + c) * AP + lane * 4];
            float part = u4.x * w2.x + u4.y * w2.y + u4.z * w2.z + u4.w * w2.w;
            part = warp_sum(part);
            total += (part + s2b0) * seq_mask[b * CDIM + c];
        }
        if (lane == 0) out[b * NPAIR + pg0 + p] = total;
    }
}

// ---------------------------------------------------------------------------
extern "C" void kernel_launch(void* const* d_in, const int* in_sizes, int n_in,
                              void* d_out, int out_size)
{
    (void)in_sizes; (void)n_in; (void)out_size;
    const float* bi       = (const float*)d_in[0];
    const float* seq_mask = (const float*)d_in[1];
    const int*   rowA     = (const int*)  d_in[2];
    const int*   colA     = (const int*)  d_in[3];
    const float* hW  = (const float*)d_in[4];
    const float* hb  = (const float*)d_in[5];
    const float* gW  = (const float*)d_in[6];
    const float* gb  = (const float*)d_in[7];
    const float* qW  = (const float*)d_in[8];
    const float* qb  = (const float*)d_in[9];
    const float* kW  = (const float*)d_in[10];
    const float* kb  = (const float*)d_in[11];
    const float* s1W = (const float*)d_in[12];
    const float* s1b = (const float*)d_in[13];
    const float* s2W = (const float*)d_in[14];
    const float* s2b = (const float*)d_in[15];
    float* out = (float*)d_out;

    const size_t psmem = (2048 + 16384) * sizeof(float);     // 72KB
    const size_t msmem = 2 * 64 * AP * sizeof(float);        // 66KB

    cudaFuncSetAttribute(prep_kernel,  cudaFuncAttributeMaxDynamicSharedMemorySize, (int)psmem);
    cudaFuncSetAttribute(phylo_kernel, cudaFuncAttributeMaxDynamicSharedMemorySize, (int)msmem);

    prep_kernel<<<BB * RDIM + 4 + 256, 256, psmem>>>(bi, kW, kb, hW, qW, gW, s1W);
    phylo_kernel<<<dim3(NGRP, BB), NT, msmem>>>(
        bi, seq_mask, rowA, colA,
        hb, gb, qb, s1b, s2W, s2b, out);
}

// round 15
// speedup vs baseline: 2.2096x; 1.4912x over previous
#include <cuda_runtime.h>
#include <math.h>
#include <stdint.h>

#define BB     8
#define RDIM   64
#define CDIM   16
#define DDIM   128
#define NPAIR  2016
#define PPB    8
#define NGRP   (NPAIR / PPB)   // 252
#define NT     512
#define AP     132             // padded pitch (floats)

// scale = 1/sqrt(D*C) = 1/sqrt(2048)
#define SCALE  0.022097086912079608f

// fragment-ordered K projection for P3:  [b][rtile(4)][kstep(256)][lane(32)][frag(4)]
__device__ float g_k3 [BB * RDIM * CDIM * DDIM];
// fragment-ordered batch_input for P5:   [b][c(16)][mt(8)][ks(8)][lane(32)][frag(4)]
__device__ float g_bi5[BB * RDIM * CDIM * DDIM];
// fragment-ordered W^T: [w][k0g(16)][n(128)][frag8]; frag = 2*(k&3)+((k&7)>>2)
__device__ float g_wtf[4 * DDIM * DDIM];

// ---------------------------------------------------------------------------
static __device__ __forceinline__ uint32_t rna_tf32(float v) {
    uint32_t r;
    asm("cvt.rna.tf32.f32 %0, %1;" : "=r"(r) : "f"(v));
    return r;
}

static __device__ __forceinline__ void mma8(float c[4], const uint32_t a[4],
                                            const uint32_t b[2]) {
    asm volatile(
        "mma.sync.aligned.m16n8k8.row.col.f32.tf32.tf32.f32 "
        "{%0,%1,%2,%3}, {%4,%5,%6,%7}, {%8,%9}, {%0,%1,%2,%3};"
        : "+f"(c[0]), "+f"(c[1]), "+f"(c[2]), "+f"(c[3])
        : "r"(a[0]), "r"(a[1]), "r"(a[2]), "r"(a[3]), "r"(b[0]), "r"(b[1]));
}

__device__ __forceinline__ float warp_sum(float v) {
    v += __shfl_xor_sync(0xffffffffu, v, 16);
    v += __shfl_xor_sync(0xffffffffu, v, 8);
    v += __shfl_xor_sync(0xffffffffu, v, 4);
    v += __shfl_xor_sync(0xffffffffu, v, 2);
    v += __shfl_xor_sync(0xffffffffu, v, 1);
    return v;
}

// ---------------------------------------------------------------------------
// Warp-tiled 128x128x128 tf32 GEMM: D = Act @ W; B-frags via LDG.64 from
// fragment-ordered g_wtf (L1-hot). 16 warps: 4 mrow x 4 ncol tiles of 32x32.
// ---------------------------------------------------------------------------
__device__ __forceinline__ void mma_gemm(const float* __restrict__ sAct,
                                         int widx,
                                         int mrow, int ncol, int gid, int tig,
                                         float acc[2][4][4])
{
    #pragma unroll
    for (int mt = 0; mt < 2; ++mt)
        #pragma unroll
        for (int nt = 0; nt < 4; ++nt)
            #pragma unroll
            for (int q = 0; q < 4; ++q) acc[mt][nt][q] = 0.f;

    const uint2* wb = (const uint2*)(g_wtf + (size_t)widx * DDIM * DDIM);

    #pragma unroll 2
    for (int k0g = 0; k0g < 16; ++k0g) {
        uint32_t a[2][4], bf[4][2];
        #pragma unroll
        for (int mt = 0; mt < 2; ++mt) {
            const float* base = sAct + (mrow + mt * 16 + gid) * AP + k0g * 8 + tig;
            a[mt][0] = rna_tf32(base[0]);
            a[mt][1] = rna_tf32(base[8 * AP]);
            a[mt][2] = rna_tf32(base[4]);
            a[mt][3] = rna_tf32(base[8 * AP + 4]);
        }
        #pragma unroll
        for (int nt = 0; nt < 4; ++nt) {
            uint2 bv = wb[(k0g * DDIM + ncol + nt * 8 + gid) * 4 + tig];
            bf[nt][0] = bv.x;
            bf[nt][1] = bv.y;
        }
        #pragma unroll
        for (int mt = 0; mt < 2; ++mt)
            #pragma unroll
            for (int nt = 0; nt < 4; ++nt)
                mma8(acc[mt][nt], a[mt], bf[nt]);
    }
}

// ---------------------------------------------------------------------------
// Prep: [0,512) K projection -> fragment-ordered g_k3;
//       [512,516) weights -> g_wtf; [516,772) bi -> fragment-ordered g_bi5
// ---------------------------------------------------------------------------
__global__ __launch_bounds__(256) void prep_kernel(
    const float* __restrict__ bi, const float* __restrict__ kW,
    const float* __restrict__ kb,
    const float* __restrict__ hW, const float* __restrict__ qW,
    const float* __restrict__ gW, const float* __restrict__ s1W)
{
    extern __shared__ float sm1[];
    const int bx = blockIdx.x;
    const int t  = threadIdx.x;

    if (bx >= BB * RDIM + 4) {     // bi -> g_bi5 (tf32 round + fragment order)
        const int w = bx - (BB * RDIM + 4);
        for (int i = t; i < 4096; i += 256) {
            int e = w * 4096 + i;
            int b = e >> 17, r = (e >> 11) & 63, c = (e >> 7) & 15, d = e & 127;
            int mt = d >> 4, gid = d & 7, f0 = (d >> 3) & 1;
            int ks = r >> 3, tig = r & 3, f1 = (r >> 2) & 1;
            int lane = (gid << 2) | tig;
            size_t idx = (((((size_t)b * 16 + c) * 8 + mt) * 8 + ks) * 32 + lane) * 4
                       + ((f1 << 1) | f0);
            g_bi5[idx] = __uint_as_float(rna_tf32(bi[e]));
        }
        return;
    }
    if (bx >= BB * RDIM) {          // weight -> fragment-ordered g_wtf
        const int w = bx - BB * RDIM;
        const float* W = (w == 0) ? hW : (w == 1) ? qW : (w == 2) ? gW : s1W;
        float* tile = sm1;          // 128*129, tile[k*129+n]
        for (int i = t; i < DDIM * DDIM; i += 256) {
            int k = i >> 7, n = i & 127;
            tile[k * 129 + n] = W[i];
        }
        __syncthreads();
        float* dst = g_wtf + (size_t)w * DDIM * DDIM;
        for (int i = t; i < DDIM * DDIM; i += 256) {
            int f   = i & 7;
            int n   = (i >> 3) & 127;
            int k0g = i >> 10;
            int k   = k0g * 8 + (f & 1) * 4 + (f >> 1);
            dst[i] = __uint_as_float(rna_tf32(tile[k * 129 + n]));
        }
        return;
    }

    // K projection for (b, r) = br; output scattered into g_k3 fragment order
    float* sx = sm1;             // 16*128
    float* sw = sm1 + 2048;      // 128*128
    const int br = bx;
    const int b  = br >> 6;
    const int r  = br & 63;

    const float4* src = (const float4*)(bi + (size_t)br * CDIM * DDIM);
    for (int i = t; i < (CDIM * DDIM) / 4; i += 256) ((float4*)sx)[i] = src[i];
    for (int i = t; i < (DDIM * DDIM) / 4; i += 256) ((float4*)sw)[i] = ((const float4*)kW)[i];
    __syncthreads();

    const int rw = t >> 4;          // c
    const int j0 = (t & 15) * 8;    // d base

    float acc[8] = {0.f,0.f,0.f,0.f,0.f,0.f,0.f,0.f};
    #pragma unroll 4
    for (int k = 0; k < DDIM; ++k) {
        float a = sx[rw * DDIM + k];
        float4 w0 = *(const float4*)&sw[k * DDIM + j0];
        float4 w1 = *(const float4*)&sw[k * DDIM + j0 + 4];
        acc[0] += a * w0.x; acc[1] += a * w0.y; acc[2] += a * w0.z; acc[3] += a * w0.w;
        acc[4] += a * w1.x; acc[5] += a * w1.y; acc[6] += a * w1.z; acc[7] += a * w1.w;
    }
    const int mtm  = r >> 4;
    const int lane_hi = (r & 7) << 2;
    const int fb0  = (r >> 3) & 1;
    #pragma unroll
    for (int q = 0; q < 8; ++q) {
        int d = j0 + q;
        int K = rw * DDIM + d;
        size_t idx = ((((size_t)b * 4 + mtm) * 256 + (K >> 3)) * 32
                     + (lane_hi | (K & 3))) * 4
                   + ((((K >> 2) & 1) << 1) | fb0);
        g_k3[idx] = __uint_as_float(rna_tf32(acc[q] + kb[d]));
    }
}

// ---------------------------------------------------------------------------
// Fused per-(batch, 8-pair) pipeline; all five contractions on tensor pipe.
// ---------------------------------------------------------------------------
__global__ __launch_bounds__(NT, 1) void phylo_kernel(
    const float* __restrict__ bi,   const float* __restrict__ seq_mask,
    const int*   __restrict__ rowA, const int*   __restrict__ colA,
    const float* __restrict__ hb,   const float* __restrict__ gb,
    const float* __restrict__ qb,   const float* __restrict__ s1b,
    const float* __restrict__ s2W,  const float* __restrict__ s2b,
    float* __restrict__ out)
{
    extern __shared__ __align__(16) float sm[];
    float* sA = sm;                    // 128*AP
    float* sB = sA + 128 * AP;         // 128*AP
    __shared__ float salpha[PPB * RDIM];
    __shared__ float sred[4][RDIM][PPB];   // P3 K-slice partials (8KB)
    __shared__ int   srow[PPB], scol[PPB];

    const int t    = threadIdx.x;
    const int b    = blockIdx.y;
    const int pg0  = blockIdx.x * PPB;
    const int warp = t >> 5;
    const int lane = t & 31;
    const int gid  = lane >> 2;        // 0..7
    const int tig  = lane & 3;         // 0..3
    const int mrow = (warp >> 2) * 32;
    const int ncol = (warp & 3) * 32;

    if (t < PPB) { srow[t] = rowA[pg0 + t]; scol[t] = colA[pg0 + t]; }
    __syncthreads();

    // sA = diff = x_i - x_j ; sB = x_j   (rows: p*16+c)
    for (int idx = t; idx < 4096; idx += NT) {
        int row = idx >> 5, d4 = idx & 31;
        int p = row >> 4, c = row & 15;
        const float4 xi = *((const float4*)(bi + (((size_t)b * RDIM + srow[p]) * CDIM + c) * DDIM) + d4);
        const float4 xj = *((const float4*)(bi + (((size_t)b * RDIM + scol[p]) * CDIM + c) * DDIM) + d4);
        *(float4*)&sA[row * AP + d4 * 4] = make_float4(xi.x - xj.x, xi.y - xj.y,
                                                       xi.z - xj.z, xi.w - xj.w);
        *(float4*)&sB[row * AP + d4 * 4] = xj;
    }
    __syncthreads();

    float acc[2][4][4];

    // ===== G1: h = diff @ hW + hb ; x = xj + sigmoid(h)*diff -> sB ==========
    mma_gemm(sA, 0, mrow, ncol, gid, tig, acc);
    #pragma unroll
    for (int nt = 0; nt < 4; ++nt) {
        int cc = ncol + nt * 8 + 2 * tig;
        float2 bb = *(const float2*)&hb[cc];
        #pragma unroll
        for (int mt = 0; mt < 2; ++mt) {
            #pragma unroll
            for (int h = 0; h < 2; ++h) {
                int row = mrow + mt * 16 + gid + 8 * h;
                float2 dv = *(float2*)&sA[row * AP + cc];
                float2 xv = *(float2*)&sB[row * AP + cc];
                float h0 = acc[mt][nt][2*h]   + bb.x;
                float h1 = acc[mt][nt][2*h+1] + bb.y;
                float z0 = 1.f / (1.f + __expf(-h0));
                float z1 = 1.f / (1.f + __expf(-h1));
                *(float2*)&sB[row * AP + cc] =
                    make_float2(xv.x + z0 * dv.x, xv.y + z1 * dv.y);
            }
        }
    }
    __syncthreads();

    // ===== G2: q = x @ qW + qb -> sA (XOR-swizzled: col ^ (((row>>4)&7)<<2)) =
    mma_gemm(sB, 1, mrow, ncol, gid, tig, acc);
    #pragma unroll
    for (int nt = 0; nt < 4; ++nt) {
        int cc = ncol + nt * 8 + 2 * tig;
        float2 bb = *(const float2*)&qb[cc];
        #pragma unroll
        for (int mt = 0; mt < 2; ++mt) {
            #pragma unroll
            for (int h = 0; h < 2; ++h) {
                int row = mrow + mt * 16 + gid + 8 * h;
                int swz = ((row >> 4) & 7) << 2;
                sA[row * AP + ((cc)     ^ swz)] = acc[mt][nt][2*h]   + bb.x;
                sA[row * AP + ((cc + 1) ^ swz)] = acc[mt][nt][2*h+1] + bb.y;
            }
        }
    }
    __syncthreads();

    // ===== P3 (tensor): alpha[r][p] = <k_r, q_p>, K=2048; A via g_k3 ========
    {
        const int mtm = warp >> 2;     // r-tile (16 rows)
        const int kc  = warp & 3;      // K slice of 512 (64 k-steps)
        float pacc[4] = {0.f, 0.f, 0.f, 0.f};
        const int sw4 = gid << 2;
        const uint4* abase = (const uint4*)(g_k3
            + (((size_t)b * 4 + mtm) * 256 + kc * 64) * 128) + lane;

        #pragma unroll 4
        for (int s = 0; s < 64; ++s) {
            uint4 av = abase[s * 32];
            uint32_t a[4] = {av.x, av.y, av.z, av.w};
            int Kg = kc * 512 + s * 8 + tig;
            int c  = Kg >> 7, d = Kg & 127;
            int rq = (gid * 16 + c) * AP;
            uint32_t bq[2];
            bq[0] = rna_tf32(sA[rq + (d ^ sw4)]);
            bq[1] = rna_tf32(sA[rq + ((d + 4) ^ sw4)]);
            mma8(pacc, a, bq);
        }
        int r0 = mtm * 16 + gid;
        sred[kc][r0][2 * tig]         = pacc[0];
        sred[kc][r0][2 * tig + 1]     = pacc[1];
        sred[kc][r0 + 8][2 * tig]     = pacc[2];
        sred[kc][r0 + 8][2 * tig + 1] = pacc[3];
    }
    __syncthreads();
    {   // reduce 4 K-slices -> salpha[p*64 + r]
        int r = t >> 3, p = t & 7;
        salpha[p * 64 + r] = (sred[0][r][p] + sred[1][r][p]
                            + sred[2][r][p] + sred[3][r][p]) * SCALE;
    }
    __syncthreads();

    // ===== P4: masked softmax over r =========================================
    if (warp < 8) {
        int p  = warp;
        int rI = srow[p], cI = scol[p];
        float v0 = salpha[p * 64 + lane];
        float v1 = salpha[p * 64 + 32 + lane];
        if (lane == rI      || lane == cI)      v0 = -INFINITY;
        if (lane + 32 == rI || lane + 32 == cI) v1 = -INFINITY;
        float mx = fmaxf(v0, v1);
        #pragma unroll
        for (int off = 16; off > 0; off >>= 1)
            mx = fmaxf(mx, __shfl_xor_sync(0xffffffffu, mx, off));
        float e0 = __expf(v0 - mx), e1 = __expf(v1 - mx);
        float s = warp_sum(e0 + e1);
        float inv = 1.f / s;
        salpha[p * 64 + lane]      = e0 * inv;
        salpha[p * 64 + 32 + lane] = e1 * inv;
    }
    __syncthreads();

    // ===== P5 (tensor): x_glob[d][p] per c = sum_r bi[r,c,d]*alpha[p][r] ====
    {
        const int c = warp;            // 16 warps <-> 16 c
        float pc5[8][4];
        #pragma unroll
        for (int mt = 0; mt < 8; ++mt)
            #pragma unroll
            for (int q = 0; q < 4; ++q) pc5[mt][q] = 0.f;

        const uint4* abase = (const uint4*)(g_bi5
            + (((size_t)b * 16 + c) * 64) * 128) + lane;
        #pragma unroll
        for (int ks = 0; ks < 8; ++ks) {
            int r = ks * 8 + tig;
            uint32_t bq[2];
            bq[0] = rna_tf32(salpha[gid * 64 + r]);
            bq[1] = rna_tf32(salpha[gid * 64 + r + 4]);
            #pragma unroll
            for (int mt = 0; mt < 8; ++mt) {
                uint4 av = abase[(mt * 8 + ks) * 32];
                uint32_t a[4] = {av.x, av.y, av.z, av.w};
                mma8(pc5[mt], a, bq);
            }
        }
        #pragma unroll
        for (int mt = 0; mt < 8; ++mt) {
            int d = mt * 16 + gid;
            int p0 = 2 * tig, p1 = 2 * tig + 1;
            sA[(p0 * 16 + c) * AP + d]     = pc5[mt][0];
            sA[(p1 * 16 + c) * AP + d]     = pc5[mt][1];
            sA[(p0 * 16 + c) * AP + d + 8] = pc5[mt][2];
            sA[(p1 * 16 + c) * AP + d + 8] = pc5[mt][3];
        }
    }
    __syncthreads();

    // ===== G3: g = x_glob @ gW + gb ; x = x + sig(g)*(x_glob - x) -> sB =====
    mma_gemm(sA, 2, mrow, ncol, gid, tig, acc);
    #pragma unroll
    for (int nt = 0; nt < 4; ++nt) {
        int cc = ncol + nt * 8 + 2 * tig;
        float2 bb = *(const float2*)&gb[cc];
        #pragma unroll
        for (int mt = 0; mt < 2; ++mt) {
            #pragma unroll
            for (int h = 0; h < 2; ++h) {
                int row = mrow + mt * 16 + gid + 8 * h;
                float2 gv = *(float2*)&sA[row * AP + cc];
                float2 xv = *(float2*)&sB[row * AP + cc];
                float g0 = acc[mt][nt][2*h]   + bb.x;
                float g1 = acc[mt][nt][2*h+1] + bb.y;
                float w0 = 1.f / (1.f + __expf(-g0));
                float w1 = 1.f / (1.f + __expf(-g1));
                *(float2*)&sB[row * AP + cc] =
                    make_float2(xv.x + w0 * (gv.x - xv.x),
                                xv.y + w1 * (gv.y - xv.y));
            }
        }
    }
    __syncthreads();

    // ===== G4: u = gelu_exact(x @ s1W + s1b) -> sA ==========================
    mma_gemm(sB, 3, mrow, ncol, gid, tig, acc);
    const float is2 = 0.70710678118654752f;
    #pragma unroll
    for (int nt = 0; nt < 4; ++nt) {
        int cc = ncol + nt * 8 + 2 * tig;
        float2 bb = *(const float2*)&s1b[cc];
        #pragma unroll
        for (int mt = 0; mt < 2; ++mt) {
            #pragma unroll
            for (int h = 0; h < 2; ++h) {
                int row = mrow + mt * 16 + gid + 8 * h;
                float u0 = acc[mt][nt][2*h]   + bb.x;
                float u1 = acc[mt][nt][2*h+1] + bb.y;
                *(float2*)&sA[row * AP + cc] =
                    make_float2(0.5f * u0 * (1.f + erff(u0 * is2)),
                                0.5f * u1 * (1.f + erff(u1 * is2)));
            }
        }
    }
    __syncthreads();

    // ===== P8: s = u @ s2W + s2b ; masked row-sum ===========================
    if (warp < 8) {
        int p = warp;
        float4 w2 = *(const float4*)&s2W[lane * 4];
        float s2b0 = s2b[0];
        float total = 0.f;
        #pragma unroll
        for (int c = 0; c < CDIM; ++c) {
            float4 u4 = *(const float4*)&sA[(p * 16 + c) * AP + lane * 4];
            float part = u4.x * w2.x + u4.y * w2.y + u4.z * w2.z + u4.w * w2.w;
            part = warp_sum(part);
            total += (part + s2b0) * seq_mask[b * CDIM + c];
        }
        if (lane == 0) out[b * NPAIR + pg0 + p] = total;
    }
}

// ---------------------------------------------------------------------------
extern "C" void kernel_launch(void* const* d_in, const int* in_sizes, int n_in,
                              void* d_out, int out_size)
{
    (void)in_sizes; (void)n_in; (void)out_size;
    const float* bi       = (const float*)d_in[0];
    const float* seq_mask = (const float*)d_in[1];
    const int*   rowA     = (const int*)  d_in[2];
    const int*   colA     = (const int*)  d_in[3];
    const float* hW  = (const float*)d_in[4];
    const float* hb  = (const float*)d_in[5];
    const float* gW  = (const float*)d_in[6];
    const float* gb  = (const float*)d_in[7];
    const float* qW  = (const float*)d_in[8];
    const float* qb  = (const float*)d_in[9];
    const float* kW  = (const float*)d_in[10];
    const float* kb  = (const float*)d_in[11];
    const float* s1W = (const float*)d_in[12];
    const float* s1b = (const float*)d_in[13];
    const float* s2W = (const float*)d_in[14];
    const float* s2b = (const float*)d_in[15];
    float* out = (float*)d_out;

    const size_t psmem = (2048 + 16384) * sizeof(float);     // 72KB
    const size_t msmem = 2 * 128 * AP * sizeof(float);       // 132KB

    cudaFuncSetAttribute(prep_kernel,  cudaFuncAttributeMaxDynamicSharedMemorySize, (int)psmem);
    cudaFuncSetAttribute(phylo_kernel, cudaFuncAttributeMaxDynamicSharedMemorySize, (int)msmem);

    prep_kernel<<<BB * RDIM + 4 + 256, 256, psmem>>>(bi, kW, kb, hW, qW, gW, s1W);
    phylo_kernel<<<dim3(NGRP, BB), NT, msmem>>>(
        bi, seq_mask, rowA, colA,
        hb, gb, qb, s1b, s2W, s2b, out);
}

// round 17
// speedup vs baseline: 2.3505x; 1.0638x over previous
#include <cuda_runtime.h>
#include <math.h>
#include <stdint.h>

#define BB     8
#define RDIM   64
#define CDIM   16
#define DDIM   128
#define NPAIR  2016
#define PPB    8
#define NGRP   (NPAIR / PPB)   // 252
#define NT     512
#define AP     132             // padded pitch (floats)

// scale = 1/sqrt(D*C) = 1/sqrt(2048)
#define SCALE  0.022097086912079608f

// fragment-ordered K projection for P3:  [b][rtile(4)][kstep(256)][lane(32)][frag(4)]
__device__ float g_k3 [BB * RDIM * CDIM * DDIM];
// fragment-ordered batch_input for P5:   [b][c(16)][mt(8)][ks(8)][lane(32)][frag(4)]
__device__ float g_bi5[BB * RDIM * CDIM * DDIM];
// fragment-ordered W^T: [w][k0g(16)][n(128)][frag8]; frag = 2*(k&3)+((k&7)>>2)
__device__ float g_wtf[4 * DDIM * DDIM];

// ---------------------------------------------------------------------------
static __device__ __forceinline__ uint32_t rna_tf32(float v) {
    uint32_t r;
    asm("cvt.rna.tf32.f32 %0, %1;" : "=r"(r) : "f"(v));
    return r;
}

static __device__ __forceinline__ void mma8(float c[4], const uint32_t a[4],
                                            const uint32_t b[2]) {
    asm volatile(
        "mma.sync.aligned.m16n8k8.row.col.f32.tf32.tf32.f32 "
        "{%0,%1,%2,%3}, {%4,%5,%6,%7}, {%8,%9}, {%0,%1,%2,%3};"
        : "+f"(c[0]), "+f"(c[1]), "+f"(c[2]), "+f"(c[3])
        : "r"(a[0]), "r"(a[1]), "r"(a[2]), "r"(a[3]), "r"(b[0]), "r"(b[1]));
}

__device__ __forceinline__ float warp_sum(float v) {
    v += __shfl_xor_sync(0xffffffffu, v, 16);
    v += __shfl_xor_sync(0xffffffffu, v, 8);
    v += __shfl_xor_sync(0xffffffffu, v, 4);
    v += __shfl_xor_sync(0xffffffffu, v, 2);
    v += __shfl_xor_sync(0xffffffffu, v, 1);
    return v;
}

// ---------------------------------------------------------------------------
// Warp-tiled 128x128x128 tf32 GEMM: D = Act @ W; B-frags via LDG.64 from
// fragment-ordered g_wtf (L1-hot, RNA-prerounded). A-frags: raw f32 bits from
// smem (HMMA.TF32 truncates to 19 bits -> implicit RZ; within error budget).
// ---------------------------------------------------------------------------
__device__ __forceinline__ void mma_gemm(const float* __restrict__ sAct,
                                         int widx,
                                         int mrow, int ncol, int gid, int tig,
                                         float acc[2][4][4])
{
    #pragma unroll
    for (int mt = 0; mt < 2; ++mt)
        #pragma unroll
        for (int nt = 0; nt < 4; ++nt)
            #pragma unroll
            for (int q = 0; q < 4; ++q) acc[mt][nt][q] = 0.f;

    const uint2* wb = (const uint2*)(g_wtf + (size_t)widx * DDIM * DDIM);

    #pragma unroll 2
    for (int k0g = 0; k0g < 16; ++k0g) {
        uint32_t a[2][4], bf[4][2];
        #pragma unroll
        for (int mt = 0; mt < 2; ++mt) {
            const float* base = sAct + (mrow + mt * 16 + gid) * AP + k0g * 8 + tig;
            a[mt][0] = __float_as_uint(base[0]);
            a[mt][1] = __float_as_uint(base[8 * AP]);
            a[mt][2] = __float_as_uint(base[4]);
            a[mt][3] = __float_as_uint(base[8 * AP + 4]);
        }
        #pragma unroll
        for (int nt = 0; nt < 4; ++nt) {
            uint2 bv = wb[(k0g * DDIM + ncol + nt * 8 + gid) * 4 + tig];
            bf[nt][0] = bv.x;
            bf[nt][1] = bv.y;
        }
        #pragma unroll
        for (int mt = 0; mt < 2; ++mt)
            #pragma unroll
            for (int nt = 0; nt < 4; ++nt)
                mma8(acc[mt][nt], a[mt], bf[nt]);
    }
}

// ---------------------------------------------------------------------------
// Prep: [0,512) K projection -> fragment-ordered g_k3;
//       [512,516) weights -> g_wtf; [516,772) bi -> fragment-ordered g_bi5
// ---------------------------------------------------------------------------
__global__ __launch_bounds__(256) void prep_kernel(
    const float* __restrict__ bi, const float* __restrict__ kW,
    const float* __restrict__ kb,
    const float* __restrict__ hW, const float* __restrict__ qW,
    const float* __restrict__ gW, const float* __restrict__ s1W)
{
    extern __shared__ float sm1[];
    const int bx = blockIdx.x;
    const int t  = threadIdx.x;

    if (bx >= BB * RDIM + 4) {     // bi -> g_bi5 (tf32 round + fragment order)
        const int w = bx - (BB * RDIM + 4);
        for (int i = t; i < 4096; i += 256) {
            int e = w * 4096 + i;
            int b = e >> 17, r = (e >> 11) & 63, c = (e >> 7) & 15, d = e & 127;
            int mt = d >> 4, gid = d & 7, f0 = (d >> 3) & 1;
            int ks = r >> 3, tig = r & 3, f1 = (r >> 2) & 1;
            int lane = (gid << 2) | tig;
            size_t idx = (((((size_t)b * 16 + c) * 8 + mt) * 8 + ks) * 32 + lane) * 4
                       + ((f1 << 1) | f0);
            g_bi5[idx] = __uint_as_float(rna_tf32(bi[e]));
        }
        return;
    }
    if (bx >= BB * RDIM) {          // weight -> fragment-ordered g_wtf
        const int w = bx - BB * RDIM;
        const float* W = (w == 0) ? hW : (w == 1) ? qW : (w == 2) ? gW : s1W;
        float* tile = sm1;          // 128*129, tile[k*129+n]
        for (int i = t; i < DDIM * DDIM; i += 256) {
            int k = i >> 7, n = i & 127;
            tile[k * 129 + n] = W[i];
        }
        __syncthreads();
        float* dst = g_wtf + (size_t)w * DDIM * DDIM;
        for (int i = t; i < DDIM * DDIM; i += 256) {
            int f   = i & 7;
            int n   = (i >> 3) & 127;
            int k0g = i >> 10;
            int k   = k0g * 8 + (f & 1) * 4 + (f >> 1);
            dst[i] = __uint_as_float(rna_tf32(tile[k * 129 + n]));
        }
        return;
    }

    // K projection for (b, r) = br; output scattered into g_k3 fragment order
    float* sx = sm1;             // 16*128
    float* sw = sm1 + 2048;      // 128*128
    const int br = bx;
    const int b  = br >> 6;
    const int r  = br & 63;

    const float4* src = (const float4*)(bi + (size_t)br * CDIM * DDIM);
    for (int i = t; i < (CDIM * DDIM) / 4; i += 256) ((float4*)sx)[i] = src[i];
    for (int i = t; i < (DDIM * DDIM) / 4; i += 256) ((float4*)sw)[i] = ((const float4*)kW)[i];
    __syncthreads();

    const int rw = t >> 4;          // c
    const int j0 = (t & 15) * 8;    // d base

    float acc[8] = {0.f,0.f,0.f,0.f,0.f,0.f,0.f,0.f};
    #pragma unroll 4
    for (int k = 0; k < DDIM; ++k) {
        float a = sx[rw * DDIM + k];
        float4 w0 = *(const float4*)&sw[k * DDIM + j0];
        float4 w1 = *(const float4*)&sw[k * DDIM + j0 + 4];
        acc[0] += a * w0.x; acc[1] += a * w0.y; acc[2] += a * w0.z; acc[3] += a * w0.w;
        acc[4] += a * w1.x; acc[5] += a * w1.y; acc[6] += a * w1.z; acc[7] += a * w1.w;
    }
    const int mtm  = r >> 4;
    const int lane_hi = (r & 7) << 2;
    const int fb0  = (r >> 3) & 1;
    #pragma unroll
    for (int q = 0; q < 8; ++q) {
        int d = j0 + q;
        int K = rw * DDIM + d;
        size_t idx = ((((size_t)b * 4 + mtm) * 256 + (K >> 3)) * 32
                     + (lane_hi | (K & 3))) * 4
                   + ((((K >> 2) & 1) << 1) | fb0);
        g_k3[idx] = __uint_as_float(rna_tf32(acc[q] + kb[d]));
    }
}

// ---------------------------------------------------------------------------
// Fused per-(batch, 8-pair) pipeline; all five contractions on tensor pipe.
// ---------------------------------------------------------------------------
__global__ __launch_bounds__(NT, 1) void phylo_kernel(
    const float* __restrict__ bi,   const float* __restrict__ seq_mask,
    const int*   __restrict__ rowA, const int*   __restrict__ colA,
    const float* __restrict__ hb,   const float* __restrict__ gb,
    const float* __restrict__ qb,   const float* __restrict__ s1b,
    const float* __restrict__ s2W,  const float* __restrict__ s2b,
    float* __restrict__ out)
{
    extern __shared__ __align__(16) float sm[];
    float* sA = sm;                    // 128*AP
    float* sB = sA + 128 * AP;         // 128*AP
    __shared__ float salpha[PPB * RDIM];
    __shared__ float sred[4][RDIM][PPB];   // P3 K-slice partials (8KB)
    __shared__ int   srow[PPB], scol[PPB];

    const int t    = threadIdx.x;
    const int b    = blockIdx.y;
    const int pg0  = blockIdx.x * PPB;
    const int warp = t >> 5;
    const int lane = t & 31;
    const int gid  = lane >> 2;        // 0..7
    const int tig  = lane & 3;         // 0..3
    const int mrow = (warp >> 2) * 32;
    const int ncol = (warp & 3) * 32;

    if (t < PPB) { srow[t] = rowA[pg0 + t]; scol[t] = colA[pg0 + t]; }
    __syncthreads();

    // sA = diff = x_i - x_j ; sB = x_j   (rows: p*16+c)
    for (int idx = t; idx < 4096; idx += NT) {
        int row = idx >> 5, d4 = idx & 31;
        int p = row >> 4, c = row & 15;
        const float4 xi = *((const float4*)(bi + (((size_t)b * RDIM + srow[p]) * CDIM + c) * DDIM) + d4);
        const float4 xj = *((const float4*)(bi + (((size_t)b * RDIM + scol[p]) * CDIM + c) * DDIM) + d4);
        *(float4*)&sA[row * AP + d4 * 4] = make_float4(xi.x - xj.x, xi.y - xj.y,
                                                       xi.z - xj.z, xi.w - xj.w);
        *(float4*)&sB[row * AP + d4 * 4] = xj;
    }
    __syncthreads();

    float acc[2][4][4];

    // ===== G1: h = diff @ hW + hb ; x = xj + sigmoid(h)*diff -> sB ==========
    mma_gemm(sA, 0, mrow, ncol, gid, tig, acc);
    #pragma unroll
    for (int nt = 0; nt < 4; ++nt) {
        int cc = ncol + nt * 8 + 2 * tig;
        float2 bb = *(const float2*)&hb[cc];
        #pragma unroll
        for (int mt = 0; mt < 2; ++mt) {
            #pragma unroll
            for (int h = 0; h < 2; ++h) {
                int row = mrow + mt * 16 + gid + 8 * h;
                float2 dv = *(float2*)&sA[row * AP + cc];
                float2 xv = *(float2*)&sB[row * AP + cc];
                float h0 = acc[mt][nt][2*h]   + bb.x;
                float h1 = acc[mt][nt][2*h+1] + bb.y;
                float z0 = 1.f / (1.f + __expf(-h0));
                float z1 = 1.f / (1.f + __expf(-h1));
                *(float2*)&sB[row * AP + cc] =
                    make_float2(xv.x + z0 * dv.x, xv.y + z1 * dv.y);
            }
        }
    }
    __syncthreads();

    // ===== G2: q = x @ qW + qb -> sA (XOR-swizzled: col ^ (((row>>4)&7)<<2)) =
    mma_gemm(sB, 1, mrow, ncol, gid, tig, acc);
    #pragma unroll
    for (int nt = 0; nt < 4; ++nt) {
        int cc = ncol + nt * 8 + 2 * tig;
        float2 bb = *(const float2*)&qb[cc];
        #pragma unroll
        for (int mt = 0; mt < 2; ++mt) {
            #pragma unroll
            for (int h = 0; h < 2; ++h) {
                int row = mrow + mt * 16 + gid + 8 * h;
                int swz = ((row >> 4) & 7) << 2;
                sA[row * AP + ((cc)     ^ swz)] = acc[mt][nt][2*h]   + bb.x;
                sA[row * AP + ((cc + 1) ^ swz)] = acc[mt][nt][2*h+1] + bb.y;
            }
        }
    }
    __syncthreads();

    // ===== P3 (tensor): alpha[r][p] = <k_r, q_p>, K=2048; A via g_k3 ========
    // c-blocked: q-row pointer hoisted, d-steps fully unrolled.
    {
        const int mtm = warp >> 2;     // r-tile (16 rows)
        const int kc  = warp & 3;      // K slice of 512 (4 c-values)
        float pacc[4] = {0.f, 0.f, 0.f, 0.f};
        const int sw4 = gid << 2;
        const uint4* abase = (const uint4*)(g_k3
            + (((size_t)b * 4 + mtm) * 256 + kc * 64) * 128) + lane;

        #pragma unroll
        for (int cb = 0; cb < 4; ++cb) {
            const int c = kc * 4 + cb;
            const float* qrow = sA + (gid * 16 + c) * AP;
            #pragma unroll
            for (int s2 = 0; s2 < 16; ++s2) {
                uint4 av = abase[(cb * 16 + s2) * 32];
                uint32_t a[4] = {av.x, av.y, av.z, av.w};
                int d = s2 * 8 + tig;
                uint32_t bq[2];
                bq[0] = __float_as_uint(qrow[d ^ sw4]);
                bq[1] = __float_as_uint(qrow[(d + 4) ^ sw4]);
                mma8(pacc, a, bq);
            }
        }
        int r0 = mtm * 16 + gid;
        sred[kc][r0][2 * tig]         = pacc[0];
        sred[kc][r0][2 * tig + 1]     = pacc[1];
        sred[kc][r0 + 8][2 * tig]     = pacc[2];
        sred[kc][r0 + 8][2 * tig + 1] = pacc[3];
    }
    __syncthreads();
    {   // reduce 4 K-slices -> salpha[p*64 + r]
        int r = t >> 3, p = t & 7;
        salpha[p * 64 + r] = (sred[0][r][p] + sred[1][r][p]
                            + sred[2][r][p] + sred[3][r][p]) * SCALE;
    }
    __syncthreads();

    // ===== P4: masked softmax over r =========================================
    if (warp < 8) {
        int p  = warp;
        int rI = srow[p], cI = scol[p];
        float v0 = salpha[p * 64 + lane];
        float v1 = salpha[p * 64 + 32 + lane];
        if (lane == rI      || lane == cI)      v0 = -INFINITY;
        if (lane + 32 == rI || lane + 32 == cI) v1 = -INFINITY;
        float mx = fmaxf(v0, v1);
        #pragma unroll
        for (int off = 16; off > 0; off >>= 1)
            mx = fmaxf(mx, __shfl_xor_sync(0xffffffffu, mx, off));
        float e0 = __expf(v0 - mx), e1 = __expf(v1 - mx);
        float s = warp_sum(e0 + e1);
        float inv = 1.f / s;
        salpha[p * 64 + lane]      = e0 * inv;
        salpha[p * 64 + 32 + lane] = e1 * inv;
    }
    __syncthreads();

    // ===== P5 (tensor): x_glob[d][p] per c = sum_r bi[r,c,d]*alpha[p][r] ====
    {
        const int c = warp;            // 16 warps <-> 16 c
        float pc5[8][4];
        #pragma unroll
        for (int mt = 0; mt < 8; ++mt)
            #pragma unroll
            for (int q = 0; q < 4; ++q) pc5[mt][q] = 0.f;

        const uint4* abase = (const uint4*)(g_bi5
            + (((size_t)b * 16 + c) * 64) * 128) + lane;
        const float* arow = salpha + gid * 64;
        #pragma unroll
        for (int ks = 0; ks < 8; ++ks) {
            int r = ks * 8 + tig;
            uint32_t bq[2];
            bq[0] = __float_as_uint(arow[r]);
            bq[1] = __float_as_uint(arow[r + 4]);
            #pragma unroll
            for (int mt = 0; mt < 8; ++mt) {
                uint4 av = abase[(mt * 8 + ks) * 32];
                uint32_t a[4] = {av.x, av.y, av.z, av.w};
                mma8(pc5[mt], a, bq);
            }
        }
        #pragma unroll
        for (int mt = 0; mt < 8; ++mt) {
            int d = mt * 16 + gid;
            int p0 = 2 * tig, p1 = 2 * tig + 1;
            sA[(p0 * 16 + c) * AP + d]     = pc5[mt][0];
            sA[(p1 * 16 + c) * AP + d]     = pc5[mt][1];
            sA[(p0 * 16 + c) * AP + d + 8] = pc5[mt][2];
            sA[(p1 * 16 + c) * AP + d + 8] = pc5[mt][3];
        }
    }
    __syncthreads();

    // ===== G3: g = x_glob @ gW + gb ; x = x + sig(g)*(x_glob - x) -> sB =====
    mma_gemm(sA, 2, mrow, ncol, gid, tig, acc);
    #pragma unroll
    for (int nt = 0; nt < 4; ++nt) {
        int cc = ncol + nt * 8 + 2 * tig;
        float2 bb = *(const float2*)&gb[cc];
        #pragma unroll
        for (int mt = 0; mt < 2; ++mt) {
            #pragma unroll
            for (int h = 0; h < 2; ++h) {
                int row = mrow + mt * 16 + gid + 8 * h;
                float2 gv = *(float2*)&sA[row * AP + cc];
                float2 xv = *(float2*)&sB[row * AP + cc];
                float g0 = acc[mt][nt][2*h]   + bb.x;
                float g1 = acc[mt][nt][2*h+1] + bb.y;
                float w0 = 1.f / (1.f + __expf(-g0));
                float w1 = 1.f / (1.f + __expf(-g1));
                *(float2*)&sB[row * AP + cc] =
                    make_float2(xv.x + w0 * (gv.x - xv.x),
                                xv.y + w1 * (gv.y - xv.y));
            }
        }
    }
    __syncthreads();

    // ===== G4: u = gelu_exact(x @ s1W + s1b) -> sA ==========================
    mma_gemm(sB, 3, mrow, ncol, gid, tig, acc);
    const float is2 = 0.70710678118654752f;
    #pragma unroll
    for (int nt = 0; nt < 4; ++nt) {
        int cc = ncol + nt * 8 + 2 * tig;
        float2 bb = *(const float2*)&s1b[cc];
        #pragma unroll
        for (int mt = 0; mt < 2; ++mt) {
            #pragma unroll
            for (int h = 0; h < 2; ++h) {
                int row = mrow + mt * 16 + gid + 8 * h;
                float u0 = acc[mt][nt][2*h]   + bb.x;
                float u1 = acc[mt][nt][2*h+1] + bb.y;
                *(float2*)&sA[row * AP + cc] =
                    make_float2(0.5f * u0 * (1.f + erff(u0 * is2)),
                                0.5f * u1 * (1.f + erff(u1 * is2)));
            }
        }
    }
    __syncthreads();

    // ===== P8: s = u @ s2W + s2b ; masked row-sum ===========================
    if (warp < 8) {
        int p = warp;
        float4 w2 = *(const float4*)&s2W[lane * 4];
        float s2b0 = s2b[0];
        float total = 0.f;
        #pragma unroll
        for (int c = 0; c < CDIM; ++c) {
            float4 u4 = *(const float4*)&sA[(p * 16 + c) * AP + lane * 4];
            float part = u4.x * w2.x + u4.y * w2.y + u4.z * w2.z + u4.w * w2.w;
            part = warp_sum(part);
            total += (part + s2b0) * seq_mask[b * CDIM + c];
        }
        if (lane == 0) out[b * NPAIR + pg0 + p] = total;
    }
}

// ---------------------------------------------------------------------------
extern "C" void kernel_launch(void* const* d_in, const int* in_sizes, int n_in,
                              void* d_out, int out_size)
{
    (void)in_sizes; (void)n_in; (void)out_size;
    const float* bi       = (const float*)d_in[0];
    const float* seq_mask = (const float*)d_in[1];
    const int*   rowA     = (const int*)  d_in[2];
    const int*   colA     = (const int*)  d_in[3];
    const float* hW  = (const float*)d_in[4];
    const float* hb  = (const float*)d_in[5];
    const float* gW  = (const float*)d_in[6];
    const float* gb  = (const float*)d_in[7];
    const float* qW  = (const float*)d_in[8];
    const float* qb  = (const float*)d_in[9];
    const float* kW  = (const float*)d_in[10];
    const float* kb  = (const float*)d_in[11];
    const float* s1W = (const float*)d_in[12];
    const float* s1b = (const float*)d_in[13];
    const float* s2W = (const float*)d_in[14];
    const float* s2b = (const float*)d_in[15];
    float* out = (float*)d_out;

    const size_t psmem = (2048 + 16384) * sizeof(float);     // 72KB
    const size_t msmem = 2 * 128 * AP * sizeof(float);       // 132KB

    cudaFuncSetAttribute(prep_kernel,  cudaFuncAttributeMaxDynamicSharedMemorySize, (int)psmem);
    cudaFuncSetAttribute(phylo_kernel, cudaFuncAttributeMaxDynamicSharedMemorySize, (int)msmem);

    prep_kernel<<<BB * RDIM + 4 + 256, 256, psmem>>>(bi, kW, kb, hW, qW, gW, s1W);
    phylo_kernel<<<dim3(NGRP, BB), NT, msmem>>>(
        bi, seq_mask, rowA, colA,
        hb, gb, qb, s1b, s2W, s2b, out);
}